// round 12
// baseline (speedup 1.0000x reference)
#include <cuda_runtime.h>
#include <cuda_bf16.h>
#include <cstdint>

#define NROWS 65536
#define KDIM  512
#define DDIM  512

// ---------------- device scratch (allocation-free) ----------------
__device__ __nv_bfloat16 g_Ph[(size_t)NROWS * DDIM];
__device__ __nv_bfloat16 g_Pl[(size_t)NROWS * DDIM];
__device__ __nv_bfloat16 g_Hh[(size_t)NROWS * DDIM];
__device__ __nv_bfloat16 g_Hl[(size_t)NROWS * DDIM];
__device__ float         g_V [(size_t)NROWS * DDIM];
__device__ __nv_bfloat16 g_Wh[4][512 * 512];
__device__ __nv_bfloat16 g_Wl[4][512 * 512];

// ---------------- PTX helpers (baseline sm_80+, no 'a'-arch features) ----------------
__device__ __forceinline__ uint32_t smem_u32(const void* p) {
    uint32_t a;
    asm("{ .reg .u64 t; cvta.to.shared.u64 t, %1; cvt.u32.u64 %0, t; }" : "=r"(a) : "l"(p));
    return a;
}
__device__ __forceinline__ void ldsm4(uint32_t& r0, uint32_t& r1, uint32_t& r2, uint32_t& r3,
                                      uint32_t addr) {
    asm volatile("ldmatrix.sync.aligned.m8n8.x4.shared.b16 {%0,%1,%2,%3}, [%4];"
                 : "=r"(r0), "=r"(r1), "=r"(r2), "=r"(r3) : "r"(addr));
}
__device__ __forceinline__ void mma_bf16(float* c, const uint32_t* a, const uint32_t* b) {
    asm volatile("mma.sync.aligned.m16n8k16.row.col.f32.bf16.bf16.f32 "
                 "{%0,%1,%2,%3}, {%4,%5,%6,%7}, {%8,%9}, {%0,%1,%2,%3};"
                 : "+f"(c[0]), "+f"(c[1]), "+f"(c[2]), "+f"(c[3])
                 : "r"(a[0]), "r"(a[1]), "r"(a[2]), "r"(a[3]), "r"(b[0]), "r"(b[1]));
}
#define CPA16(dst, src)  asm volatile("cp.async.cg.shared.global [%0], [%1], 16;" :: "r"(dst), "l"(src) : "memory")
#define CPA_COMMIT()     asm volatile("cp.async.commit_group;" ::: "memory")
#define CPA_WAIT1()      asm volatile("cp.async.wait_group 1;" ::: "memory")
#define CPA_WAIT0()      asm volatile("cp.async.wait_group 0;" ::: "memory")

// round-to-nearest bf16 hi/lo split of a float pair, packed (low half = a)
__device__ __forceinline__ void split2(float a, float b, uint32_t& h, uint32_t& l) {
    asm("cvt.rn.bf16x2.f32 %0, %1, %2;" : "=r"(h) : "f"(b), "f"(a));
    float ah = __uint_as_float(h << 16);
    float bh = __uint_as_float(h & 0xFFFF0000u);
    asm("cvt.rn.bf16x2.f32 %0, %1, %2;" : "=r"(l) : "f"(b - bh), "f"(a - ah));
}
__device__ __forceinline__ float bflo(uint32_t x) { return __uint_as_float(x << 16); }
__device__ __forceinline__ float bfhi(uint32_t x) { return __uint_as_float(x & 0xFFFF0000u); }

// ---------------- layout constants ----------------
constexpr int BM = 128, BN = 64, KC = 32, KT = KDIM / KC;   // 16 k-chunks
constexpr int NTH = 256;
constexpr int NSTAGE = 3;
// 64B rows (32 bf16), XOR swizzle on 16B quads: q' = q ^ ((row>>1)&3)  (R10-verified).
constexpr int OPB_A = 128 * 64;             // 8192 per A half
constexpr int OPB_B = 64 * 64;              // 4096 per B half
constexpr int OFF_AHI = 0;
constexpr int OFF_ALO = OPB_A;
constexpr int OFF_BHI = 2 * OPB_A;
constexpr int OFF_BLO = 2 * OPB_A + OPB_B;
constexpr int STAGE_BYTES = 2 * OPB_A + 2 * OPB_B;    // 24576
constexpr int SM_STAGE = 1024;               // bn coeffs live in [0,1024)
constexpr int SM_TOTAL = SM_STAGE + NSTAGE * STAGE_BYTES;  // 74752 -> 2 CTAs/SM

__device__ __forceinline__ uint32_t swq(int row, int q) {
    return (uint32_t)((row << 6) + ((q ^ ((row >> 1) & 3)) << 4));
}

// ---------------- weight split prep ----------------
__global__ void split_weights(const float* __restrict__ w0, const float* __restrict__ w1,
                              const float* __restrict__ w2, const float* __restrict__ w3) {
    int idx = blockIdx.x * blockDim.x + threadIdx.x;
    int mat = idx >> 18;
    int off = idx & 0x3FFFF;
    const float* s = (mat == 0) ? w0 : (mat == 1) ? w1 : (mat == 2) ? w2 : w3;
    float x = s[off];
    __nv_bfloat16 h = __float2bfloat16_rn(x);
    g_Wh[mat][off] = h;
    g_Wl[mat][off] = __float2bfloat16_rn(x - __bfloat162float(h));
}

// ---------------- split-bf16 HMMA GEMM, k-split warps, 3-stage 1-sync, 2 CTAs/SM ----------------
// D[n,d] = epi( sum_k A[n,k] * B[d,k] )
// AMODE 0: A fp32 (split in-kernel)    AMODE 1: A preconverted hi/lo bf16
// EPI 0: relu -> OutH/OutL      EPI 1: relu(bn) -> OutH/OutL
// EPI 2: relu(bn) -> OutF       EPI 3: OutF = Vf + (Ph+Pl)*sigmoid(acc)
template <int AMODE, int EPI>
__global__ __launch_bounds__(NTH, 2)
void gemm_hmma(const float* __restrict__ Af,
               const __nv_bfloat16* __restrict__ Ah, const __nv_bfloat16* __restrict__ Al,
               const __nv_bfloat16* __restrict__ Bh, const __nv_bfloat16* __restrict__ Bl,
               float* __restrict__ OutF,
               __nv_bfloat16* __restrict__ OutH, __nv_bfloat16* __restrict__ OutL,
               const float* __restrict__ bng, const float* __restrict__ bnb,
               const float* __restrict__ bnm, const float* __restrict__ bnv,
               const __nv_bfloat16* __restrict__ Ph, const __nv_bfloat16* __restrict__ Pl,
               const float* __restrict__ Vf)
{
    extern __shared__ char smem[];
    const uint32_t sb = smem_u32(smem);
    const int tid = threadIdx.x;
    const int wid = tid >> 5, lid = tid & 31;
    const int bxc = blockIdx.x * BN;
    const int bym = blockIdx.y * BM;
    // 8 warps = 2(m) x 2(n) x 2(k-split); warp tile 64x32, k16-step = kh
    const int wm = (wid >> 2) * 64;
    const int wn = ((wid >> 1) & 1) * 32;
    const int kh = wid & 1;

    if ((EPI == 1 || EPI == 2) && tid < BN) {
        int c = bxc + tid;
        float iv = bng[c] * rsqrtf(bnv[c] + 1e-5f);
        ((float*)smem)[tid]         = iv;
        ((float*)(smem + 512))[tid] = bnb[c] - bnm[c] * iv;
    }

    // lane row/quad decomposition for ldsm
    const int aRow = lid & 15;                       // + wm + mf*16
    const int aQ   = lid >> 4;                       // + 2*kh
    const int bRow = (lid & 7) + ((lid >> 4) << 3);  // + wn + p*16
    const int bQ   = (lid & 8) >> 3;                 // + 2*kh

    // ---- load issue helpers ----
    auto issueB = [&](int kt, uint32_t stu) {
        int q = tid;                           // 256 16B chunks per half
        int row = q >> 2, kc = q & 3;
        size_t e = (size_t)(bxc + row) * KDIM + kt * KC + kc * 8;
        uint32_t d = swq(row, kc);
        CPA16(stu + OFF_BHI + d, (const char*)Bh + 2 * e);
        CPA16(stu + OFF_BLO + d, (const char*)Bl + 2 * e);
    };
    auto issueA1 = [&](int kt, uint32_t stu) {
#pragma unroll
        for (int i = 0; i < 2; i++) {
            int q = tid + i * NTH;             // 512 16B chunks per half
            int row = q >> 2, kc = q & 3;
            size_t e = (size_t)(bym + row) * KDIM + kt * KC + kc * 8;
            uint32_t d = swq(row, kc);
            CPA16(stu + OFF_AHI + d, (const char*)Ah + 2 * e);
            CPA16(stu + OFF_ALO + d, (const char*)Al + 2 * e);
        }
    };
    auto ldA0 = [&](int kt, float4* aReg) {
#pragma unroll
        for (int i = 0; i < 4; i++) {
            int f = tid + i * NTH;             // 1024 float4 slots (128 rows x 8)
            int row = f >> 3, kq = f & 7;
            aReg[i] = *(const float4*)(Af + (size_t)(bym + row) * KDIM + kt * KC + kq * 4);
        }
    };
    auto stsA0 = [&](char* st, const float4* aReg) {
#pragma unroll
        for (int i = 0; i < 4; i++) {
            int f = tid + i * NTH;
            int row = f >> 3, kq = f & 7;      // 8B units
            uint32_t h01, l01, h23, l23;
            split2(aReg[i].x, aReg[i].y, h01, l01);
            split2(aReg[i].z, aReg[i].w, h23, l23);
            uint32_t d = swq(row, kq >> 1) + (kq & 1) * 8;
            *(uint2*)(st + OFF_AHI + d) = make_uint2(h01, h23);
            *(uint2*)(st + OFF_ALO + d) = make_uint2(l01, l23);
        }
    };

    // ---- prologue: fill stages 0 and 1 (groups #0, #1) ----
#pragma unroll
    for (int pk = 0; pk < NSTAGE - 1; pk++) {
        char* st = smem + SM_STAGE + pk * STAGE_BYTES;
        uint32_t stu = sb + SM_STAGE + pk * STAGE_BYTES;
        if (AMODE == 0) {
            float4 aR[4];
            ldA0(pk, aR);
            stsA0(st, aR);
        } else {
            issueA1(pk, stu);
        }
        issueB(pk, stu);
        CPA_COMMIT();
    }

    // ---- mainloop: R10-verified order  WAIT -> sync -> refill -> commit -> compute ----
    float acc[4][4][4];
#pragma unroll
    for (int mf = 0; mf < 4; mf++)
#pragma unroll
        for (int j = 0; j < 4; j++)
#pragma unroll
            for (int e = 0; e < 4; e++) acc[mf][j][e] = 0.f;

    float4 aReg[4];
    for (int kt = 0; kt < KT; kt++) {
        const int s = kt % NSTAGE;
        const uint32_t s0 = sb + SM_STAGE + s * STAGE_BYTES;
        const int kpre = kt + NSTAGE - 1;

        if (AMODE == 0 && kpre < KT) ldA0(kpre, aReg);   // hoisted LDG above the wait

        CPA_WAIT1();           // my groups through chunk kt complete
        __syncthreads();       // everyone waited -> chunk kt visible; stage (kt-1)%3 free

        if (kpre < KT) {       // refill the freed slot
            const int slot = kpre % NSTAGE;
            char* st = smem + SM_STAGE + slot * STAGE_BYTES;
            uint32_t stu = sb + SM_STAGE + slot * STAGE_BYTES;
            if (AMODE == 0) stsA0(st, aReg);
            else            issueA1(kpre, stu);
            issueB(kpre, stu);
        }
        CPA_COMMIT();          // empty groups at tail keep accounting uniform

        // ---- compute chunk kt: this warp's k16-step (ks = kh); A-lo reuses A-hi regs ----
        {
            uint32_t bh[4][2], bl[4][2], af[4][4];
#pragma unroll
            for (int p = 0; p < 2; p++) {
                int row = wn + p * 16 + bRow;
                uint32_t ad = s0 + swq(row, 2 * kh + bQ);
                ldsm4(bh[2*p][0], bh[2*p][1], bh[2*p+1][0], bh[2*p+1][1], ad + OFF_BHI);
                ldsm4(bl[2*p][0], bl[2*p][1], bl[2*p+1][0], bl[2*p+1][1], ad + OFF_BLO);
            }
#pragma unroll
            for (int mf = 0; mf < 4; mf++) {
                int row = wm + mf * 16 + aRow;
                ldsm4(af[mf][0], af[mf][1], af[mf][2], af[mf][3],
                      s0 + OFF_AHI + swq(row, 2 * kh + aQ));
            }
#pragma unroll
            for (int mf = 0; mf < 4; mf++)
#pragma unroll
                for (int j = 0; j < 4; j++) mma_bf16(acc[mf][j], af[mf], bh[j]);
#pragma unroll
            for (int mf = 0; mf < 4; mf++)
#pragma unroll
                for (int j = 0; j < 4; j++) mma_bf16(acc[mf][j], af[mf], bl[j]);
#pragma unroll
            for (int mf = 0; mf < 4; mf++) {
                int row = wm + mf * 16 + aRow;
                ldsm4(af[mf][0], af[mf][1], af[mf][2], af[mf][3],
                      s0 + OFF_ALO + swq(row, 2 * kh + aQ));
            }
#pragma unroll
            for (int mf = 0; mf < 4; mf++)
#pragma unroll
                for (int j = 0; j < 4; j++) mma_bf16(acc[mf][j], af[mf], bh[j]);
        }
    }
    CPA_WAIT0();
    __syncthreads();

    // ---- k-split merge via SMEM exchange ----
    // Warp (m,n,kh) outputs bands {2kh, 2kh+1}; stores the other two for its partner.
    {
        float* xch = (float*)(smem + SM_STAGE);
        const int pos = wid >> 1;                 // (m,n) position 0..3
        const int mfO = kh * 2;
        const int mfX = 2 - kh * 2;
        float* mybuf = xch + (size_t)(pos * 2 + kh) * 1024;
#pragma unroll
        for (int m2 = 0; m2 < 2; m2++)
#pragma unroll
            for (int j = 0; j < 4; j++)
#pragma unroll
                for (int e = 0; e < 4; e++)
                    mybuf[((m2 * 4 + j) * 4 + e) * 32 + lid] = acc[mfX + m2][j][e];
        __syncthreads();
        const float* pbuf = xch + (size_t)(pos * 2 + (1 - kh)) * 1024;
#pragma unroll
        for (int m2 = 0; m2 < 2; m2++)
#pragma unroll
            for (int j = 0; j < 4; j++)
#pragma unroll
                for (int e = 0; e < 4; e++)
                    acc[mfO + m2][j][e] += pbuf[((m2 * 4 + j) * 4 + e) * 32 + lid];
    }

    // ---- epilogue: merged fragments -> global ----
    const float* invv = (const float*)smem;
    const float* addv = (const float*)(smem + 512);
    const int mfO = kh * 2;
#pragma unroll
    for (int m2 = 0; m2 < 2; m2++) {
        const int mf = mfO + m2;
#pragma unroll
        for (int j = 0; j < 4; j++) {
            const float* a = acc[mf][j];
            const int rg = bym + wm + mf * 16 + (lid >> 2);
            const int cl = wn + j * 8 + (lid & 3) * 2;
            const int cg = bxc + cl;
#pragma unroll
            for (int half = 0; half < 2; half++) {
                const int r = rg + half * 8;
                float v0 = a[half * 2 + 0], v1 = a[half * 2 + 1];
                const size_t go = (size_t)r * DDIM + cg;
                if (EPI == 0) {
                    v0 = fmaxf(v0, 0.f); v1 = fmaxf(v1, 0.f);
                    uint32_t h, l; split2(v0, v1, h, l);
                    *(uint32_t*)((char*)OutH + 2 * go) = h;
                    *(uint32_t*)((char*)OutL + 2 * go) = l;
                } else if (EPI == 1) {
                    v0 = fmaxf(fmaf(v0, invv[cl], addv[cl]), 0.f);
                    v1 = fmaxf(fmaf(v1, invv[cl + 1], addv[cl + 1]), 0.f);
                    uint32_t h, l; split2(v0, v1, h, l);
                    *(uint32_t*)((char*)OutH + 2 * go) = h;
                    *(uint32_t*)((char*)OutL + 2 * go) = l;
                } else if (EPI == 2) {
                    float2 o;
                    o.x = fmaxf(fmaf(v0, invv[cl], addv[cl]), 0.f);
                    o.y = fmaxf(fmaf(v1, invv[cl + 1], addv[cl + 1]), 0.f);
                    *(float2*)(OutF + go) = o;
                } else {
                    const uint32_t hh = *(const uint32_t*)((const char*)Ph + 2 * go);
                    const uint32_t ll = *(const uint32_t*)((const char*)Pl + 2 * go);
                    const float2 vv = *(const float2*)(Vf + go);
                    const float p0 = bflo(hh) + bflo(ll);
                    const float p1 = bfhi(hh) + bfhi(ll);
                    const float s0v = 1.f / (1.f + __expf(-v0));
                    const float s1v = 1.f / (1.f + __expf(-v1));
                    float2 o;
                    o.x = fmaf(p0, s0v, vv.x);
                    o.y = fmaf(p1, s1v, vv.y);
                    *(float2*)(OutF + go) = o;
                }
            }
        }
    }
}

// ---------------- launch ----------------
extern "C" void kernel_launch(void* const* d_in, const int* in_sizes, int n_in,
                              void* d_out, int out_size)
{
    const float* F1   = (const float*)d_in[0];
    const float* F2   = (const float*)d_in[1];
    const float* Wk   = (const float*)d_in[2];
    const float* Wv1  = (const float*)d_in[3];
    const float* Wv2  = (const float*)d_in[4];
    const float* bn1g = (const float*)d_in[5];
    const float* bn1b = (const float*)d_in[6];
    const float* bn1m = (const float*)d_in[7];
    const float* bn1v = (const float*)d_in[8];
    const float* bn2g = (const float*)d_in[9];
    const float* bn2b = (const float*)d_in[10];
    const float* bn2m = (const float*)d_in[11];
    const float* bn2v = (const float*)d_in[12];
    // d_in[13]=Wa, d_in[14]=Wqk unused: softmax over identical L-columns is uniform 1/L.
    const float* Wvc  = (const float*)d_in[15];
    float* out = (float*)d_out;

    __nv_bfloat16 *Ph, *Pl, *Hh, *Hl, *Wh, *Wl;
    float* V;
    cudaGetSymbolAddress((void**)&Ph, g_Ph);
    cudaGetSymbolAddress((void**)&Pl, g_Pl);
    cudaGetSymbolAddress((void**)&Hh, g_Hh);
    cudaGetSymbolAddress((void**)&Hl, g_Hl);
    cudaGetSymbolAddress((void**)&V,  g_V);
    cudaGetSymbolAddress((void**)&Wh, g_Wh);
    cudaGetSymbolAddress((void**)&Wl, g_Wl);
    const int WSZ = 512 * 512;

    cudaFuncSetAttribute(gemm_hmma<0,0>, cudaFuncAttributeMaxDynamicSharedMemorySize, SM_TOTAL);
    cudaFuncSetAttribute(gemm_hmma<0,1>, cudaFuncAttributeMaxDynamicSharedMemorySize, SM_TOTAL);
    cudaFuncSetAttribute(gemm_hmma<1,2>, cudaFuncAttributeMaxDynamicSharedMemorySize, SM_TOTAL);
    cudaFuncSetAttribute(gemm_hmma<1,3>, cudaFuncAttributeMaxDynamicSharedMemorySize, SM_TOTAL);

    // weight hi/lo split: mat0=Wk, mat1=Wv1, mat2=Wv2, mat3=Wvc
    split_weights<<<4096, 256>>>(Wk, Wv1, Wv2, Wvc);

    dim3 grid(DDIM / BN, NROWS / BM);   // (8, 512) = 4096 CTAs
    dim3 block(NTH);

    // P(hi/lo) = split(relu(F1 @ Wk^T))
    gemm_hmma<0,0><<<grid, block, SM_TOTAL>>>(F1, nullptr, nullptr, Wh + 0 * WSZ, Wl + 0 * WSZ,
        nullptr, Ph, Pl, nullptr, nullptr, nullptr, nullptr, nullptr, nullptr, nullptr);
    // H(hi/lo) = split(relu(bn1(F2 @ Wv1^T)))
    gemm_hmma<0,1><<<grid, block, SM_TOTAL>>>(F2, nullptr, nullptr, Wh + 1 * WSZ, Wl + 1 * WSZ,
        nullptr, Hh, Hl, bn1g, bn1b, bn1m, bn1v, nullptr, nullptr, nullptr);
    // V = relu(bn2(H @ Wv2^T))
    gemm_hmma<1,2><<<grid, block, SM_TOTAL>>>(nullptr, Hh, Hl, Wh + 2 * WSZ, Wl + 2 * WSZ,
        V, nullptr, nullptr, bn2g, bn2b, bn2m, bn2v, nullptr, nullptr, nullptr);
    // out = V + P * sigmoid(P @ Wvc^T)
    gemm_hmma<1,3><<<grid, block, SM_TOTAL>>>(nullptr, Ph, Pl, Wh + 3 * WSZ, Wl + 3 * WSZ,
        out, nullptr, nullptr, nullptr, nullptr, nullptr, nullptr, Ph, Pl, V);
}

// round 13
// speedup vs baseline: 2.7457x; 2.7457x over previous
#include <cuda_runtime.h>
#include <cuda_bf16.h>
#include <cstdint>

#define NROWS 65536
#define KDIM  512
#define DDIM  512

// ---------------- device scratch (allocation-free) ----------------
__device__ __nv_bfloat16 g_Ph[(size_t)NROWS * DDIM];
__device__ __nv_bfloat16 g_Pl[(size_t)NROWS * DDIM];
__device__ __nv_bfloat16 g_Hh[(size_t)NROWS * DDIM];
__device__ __nv_bfloat16 g_Hl[(size_t)NROWS * DDIM];
__device__ float         g_V [(size_t)NROWS * DDIM];
__device__ __nv_bfloat16 g_Wh[4][512 * 512];
__device__ __nv_bfloat16 g_Wl[4][512 * 512];

// ---------------- PTX helpers (baseline sm_80+, no 'a'-arch features) ----------------
__device__ __forceinline__ uint32_t smem_u32(const void* p) {
    uint32_t a;
    asm("{ .reg .u64 t; cvta.to.shared.u64 t, %1; cvt.u32.u64 %0, t; }" : "=r"(a) : "l"(p));
    return a;
}
__device__ __forceinline__ void ldsm4(uint32_t& r0, uint32_t& r1, uint32_t& r2, uint32_t& r3,
                                      uint32_t addr) {
    asm volatile("ldmatrix.sync.aligned.m8n8.x4.shared.b16 {%0,%1,%2,%3}, [%4];"
                 : "=r"(r0), "=r"(r1), "=r"(r2), "=r"(r3) : "r"(addr));
}
__device__ __forceinline__ void mma_bf16(float* c, const uint32_t* a, const uint32_t* b) {
    asm volatile("mma.sync.aligned.m16n8k16.row.col.f32.bf16.bf16.f32 "
                 "{%0,%1,%2,%3}, {%4,%5,%6,%7}, {%8,%9}, {%0,%1,%2,%3};"
                 : "+f"(c[0]), "+f"(c[1]), "+f"(c[2]), "+f"(c[3])
                 : "r"(a[0]), "r"(a[1]), "r"(a[2]), "r"(a[3]), "r"(b[0]), "r"(b[1]));
}
#define CPA16(dst, src)  asm volatile("cp.async.cg.shared.global [%0], [%1], 16;" :: "r"(dst), "l"(src) : "memory")
#define CPA_COMMIT()     asm volatile("cp.async.commit_group;" ::: "memory")
#define CPA_WAIT1()      asm volatile("cp.async.wait_group 1;" ::: "memory")
#define CPA_WAIT0()      asm volatile("cp.async.wait_group 0;" ::: "memory")

// round-to-nearest bf16 hi/lo split of a float pair, packed (low half = a)
__device__ __forceinline__ void split2(float a, float b, uint32_t& h, uint32_t& l) {
    asm("cvt.rn.bf16x2.f32 %0, %1, %2;" : "=r"(h) : "f"(b), "f"(a));
    float ah = __uint_as_float(h << 16);
    float bh = __uint_as_float(h & 0xFFFF0000u);
    asm("cvt.rn.bf16x2.f32 %0, %1, %2;" : "=r"(l) : "f"(b - bh), "f"(a - ah));
}
__device__ __forceinline__ float bflo(uint32_t x) { return __uint_as_float(x << 16); }
__device__ __forceinline__ float bfhi(uint32_t x) { return __uint_as_float(x & 0xFFFF0000u); }

// ---------------- layout constants (R10-verified) ----------------
constexpr int BM = 128, BN = 128, KC = 32, KT = KDIM / KC;   // 16 k-chunks
constexpr int NTH = 256;
constexpr int NSTAGE = 3;
// 64B rows (32 bf16), XOR swizzle on 16B quads: q' = q ^ ((row>>1)&3).
constexpr int RSB = 64;
constexpr int OPB = 128 * RSB;              // 8192 per operand half
constexpr int OFF_AHI = 0, OFF_ALO = OPB, OFF_BHI = 2 * OPB, OFF_BLO = 3 * OPB;
constexpr int STAGE_BYTES = 4 * OPB;        // 32768
constexpr int SM_STAGE = 1024;              // bn coeffs live in [0,1024)
constexpr int SM_TOTAL = SM_STAGE + NSTAGE * STAGE_BYTES;   // 99328 -> 2 CTAs/SM

__device__ __forceinline__ uint32_t swq(int row, int q) {
    return (uint32_t)((row << 6) + ((q ^ ((row >> 1) & 3)) << 4));
}

// ---------------- weight split prep ----------------
__global__ void split_weights(const float* __restrict__ w0, const float* __restrict__ w1,
                              const float* __restrict__ w2, const float* __restrict__ w3) {
    int idx = blockIdx.x * blockDim.x + threadIdx.x;
    int mat = idx >> 18;
    int off = idx & 0x3FFFF;
    const float* s = (mat == 0) ? w0 : (mat == 1) ? w1 : (mat == 2) ? w2 : w3;
    float x = s[off];
    __nv_bfloat16 h = __float2bfloat16_rn(x);
    g_Wh[mat][off] = h;
    g_Wl[mat][off] = __float2bfloat16_rn(x - __bfloat162float(h));
}

// ---------------- split-bf16 HMMA GEMM, 3-stage 1-sync pipeline, 2 CTAs/SM ----------------
// D[n,d] = epi( sum_k A[n,k] * B[d,k] )
// AMODE 0: A fp32 (split in-kernel)    AMODE 1: A preconverted hi/lo bf16
// EPI 0: relu -> OutH/OutL      EPI 1: relu(bn) -> OutH/OutL
// EPI 2: relu(bn) -> OutF       EPI 3: OutF = Vf + (Ph+Pl)*sigmoid(acc)
template <int AMODE, int EPI>
__global__ __launch_bounds__(NTH, 2)
void gemm_hmma(const float* __restrict__ Af,
               const __nv_bfloat16* __restrict__ Ah, const __nv_bfloat16* __restrict__ Al,
               const __nv_bfloat16* __restrict__ Bh, const __nv_bfloat16* __restrict__ Bl,
               float* __restrict__ OutF,
               __nv_bfloat16* __restrict__ OutH, __nv_bfloat16* __restrict__ OutL,
               const float* __restrict__ bng, const float* __restrict__ bnb,
               const float* __restrict__ bnm, const float* __restrict__ bnv,
               const __nv_bfloat16* __restrict__ Ph, const __nv_bfloat16* __restrict__ Pl,
               const float* __restrict__ Vf)
{
    extern __shared__ char smem[];
    const uint32_t sb = smem_u32(smem);
    const int tid = threadIdx.x;
    const int wid = tid >> 5, lid = tid & 31;
    const int bxc = blockIdx.x * BN;
    const int bym = blockIdx.y * BM;
    const int wm = (wid >> 2) * 64;     // warp m-band
    const int wn = (wid & 3) * 32;      // warp n-band

    if ((EPI == 1 || EPI == 2) && tid < 128) {
        int c = bxc + tid;
        float iv = bng[c] * rsqrtf(bnv[c] + 1e-5f);
        ((float*)smem)[tid]         = iv;
        ((float*)(smem + 512))[tid] = bnb[c] - bnm[c] * iv;
    }

    // lane row/quad decomposition for ldsm
    const int aRow = lid & 15;                       // + wm + mf*16
    const int aQ   = lid >> 4;                       // + 2*ks
    const int bRow = (lid & 7) + ((lid >> 4) << 3);  // + wn + p*16
    const int bQ   = (lid & 8) >> 3;                 // + 2*ks

    // ---- load issue helpers ----
    auto issueB = [&](int kt, uint32_t stu) {
#pragma unroll
        for (int i = 0; i < 2; i++) {
            int q = tid + i * NTH;                 // 512 16B chunks
            int row = q >> 2, kc = q & 3;
            size_t e = (size_t)(bxc + row) * KDIM + kt * KC + kc * 8;
            uint32_t d = swq(row, kc);
            CPA16(stu + OFF_BHI + d, (const char*)Bh + 2 * e);
            CPA16(stu + OFF_BLO + d, (const char*)Bl + 2 * e);
        }
    };
    auto issueA1 = [&](int kt, uint32_t stu) {
#pragma unroll
        for (int i = 0; i < 2; i++) {
            int q = tid + i * NTH;
            int row = q >> 2, kc = q & 3;
            size_t e = (size_t)(bym + row) * KDIM + kt * KC + kc * 8;
            uint32_t d = swq(row, kc);
            CPA16(stu + OFF_AHI + d, (const char*)Ah + 2 * e);
            CPA16(stu + OFF_ALO + d, (const char*)Al + 2 * e);
        }
    };
    auto ldA0 = [&](int kt, float4* aReg) {
#pragma unroll
        for (int i = 0; i < 4; i++) {
            int f = tid + i * NTH;                 // 1024 float4 slots
            int row = f >> 3, kq = f & 7;
            aReg[i] = *(const float4*)(Af + (size_t)(bym + row) * KDIM + kt * KC + kq * 4);
        }
    };
    auto stsA0 = [&](char* st, const float4* aReg) {
#pragma unroll
        for (int i = 0; i < 4; i++) {
            int f = tid + i * NTH;
            int row = f >> 3, kq = f & 7;          // 8B units
            uint32_t h01, l01, h23, l23;
            split2(aReg[i].x, aReg[i].y, h01, l01);
            split2(aReg[i].z, aReg[i].w, h23, l23);
            uint32_t d = swq(row, kq >> 1) + (kq & 1) * 8;
            *(uint2*)(st + OFF_AHI + d) = make_uint2(h01, h23);
            *(uint2*)(st + OFF_ALO + d) = make_uint2(l01, l23);
        }
    };

    // ---- accumulators ----
    float acc[4][4][4];
#pragma unroll
    for (int mf = 0; mf < 4; mf++)
#pragma unroll
        for (int j = 0; j < 4; j++)
#pragma unroll
            for (int e = 0; e < 4; e++) acc[mf][j][e] = 0.f;

    // one k16-step of compute from stage s0 (R10-verified body; A-lo reuses A-hi regs)
    auto computeKS = [&](int ks, uint32_t s0) {
        uint32_t bh[4][2], bl[4][2], af[4][4];
#pragma unroll
        for (int p = 0; p < 2; p++) {
            int row = wn + p * 16 + bRow;
            uint32_t ad = s0 + swq(row, 2 * ks + bQ);
            ldsm4(bh[2*p][0], bh[2*p][1], bh[2*p+1][0], bh[2*p+1][1], ad + OFF_BHI);
            ldsm4(bl[2*p][0], bl[2*p][1], bl[2*p+1][0], bl[2*p+1][1], ad + OFF_BLO);
        }
#pragma unroll
        for (int mf = 0; mf < 4; mf++) {
            int row = wm + mf * 16 + aRow;
            ldsm4(af[mf][0], af[mf][1], af[mf][2], af[mf][3],
                  s0 + OFF_AHI + swq(row, 2 * ks + aQ));
        }
#pragma unroll
        for (int mf = 0; mf < 4; mf++)
#pragma unroll
            for (int j = 0; j < 4; j++) mma_bf16(acc[mf][j], af[mf], bh[j]);
#pragma unroll
        for (int mf = 0; mf < 4; mf++)
#pragma unroll
            for (int j = 0; j < 4; j++) mma_bf16(acc[mf][j], af[mf], bl[j]);
#pragma unroll
        for (int mf = 0; mf < 4; mf++) {
            int row = wm + mf * 16 + aRow;
            ldsm4(af[mf][0], af[mf][1], af[mf][2], af[mf][3],
                  s0 + OFF_ALO + swq(row, 2 * ks + aQ));
        }
#pragma unroll
        for (int mf = 0; mf < 4; mf++)
#pragma unroll
            for (int j = 0; j < 4; j++) mma_bf16(acc[mf][j], af[mf], bh[j]);
    };

    // ---- prologue: fill stages 0 and 1 (groups #0, #1) ----
#pragma unroll
    for (int pk = 0; pk < NSTAGE - 1; pk++) {
        char* st = smem + SM_STAGE + pk * STAGE_BYTES;
        uint32_t stu = sb + SM_STAGE + pk * STAGE_BYTES;
        if (AMODE == 0) {
            float4 aR[4];
            ldA0(pk, aR);
            stsA0(st, aR);
        } else {
            issueA1(pk, stu);
        }
        issueB(pk, stu);
        CPA_COMMIT();
    }

    // ---- mainloop: WAIT -> sync -> (refill placement differs by AMODE) -> compute ----
    float4 aReg[4];
    for (int kt = 0; kt < KT; kt++) {
        const int s = kt % NSTAGE;
        const uint32_t s0 = sb + SM_STAGE + s * STAGE_BYTES;
        const int kpre = kt + NSTAGE - 1;

        if (AMODE == 0 && kpre < KT) ldA0(kpre, aReg);   // hoisted LDG above the wait

        CPA_WAIT1();           // groups through chunk kt complete
        __syncthreads();       // chunk kt visible to all; stage (kt-1)%3 free

        if (AMODE == 0) {
            // R10-exact order: refill immediately (keeps aReg liveness short)
            if (kpre < KT) {
                const int slot = kpre % NSTAGE;
                stsA0(smem + SM_STAGE + slot * STAGE_BYTES, aReg);
                issueB(kpre, sb + SM_STAGE + slot * STAGE_BYTES);
            }
            CPA_COMMIT();
            computeKS(0, s0);
            computeKS(1, s0);
        } else {
            // deferred refill: post-barrier crossbar goes to ldsm first,
            // cp.async burst rides under ks=1's MMA shadow
            computeKS(0, s0);
            if (kpre < KT) {
                const int slot = kpre % NSTAGE;
                uint32_t stu = sb + SM_STAGE + slot * STAGE_BYTES;
                issueA1(kpre, stu);
                issueB(kpre, stu);
            }
            CPA_COMMIT();
            computeKS(1, s0);
        }
    }
    CPA_WAIT0();

    // ---- epilogue: fragments -> global (8-row x 32B segments, sector-aligned) ----
    const float* invv = (const float*)smem;
    const float* addv = (const float*)(smem + 512);
#pragma unroll
    for (int mf = 0; mf < 4; mf++) {
#pragma unroll
        for (int j = 0; j < 4; j++) {
            const float* a = acc[mf][j];
            const int rg = bym + wm + mf * 16 + (lid >> 2);
            const int cl = wn + j * 8 + (lid & 3) * 2;
            const int cg = bxc + cl;
#pragma unroll
            for (int half = 0; half < 2; half++) {
                const int r = rg + half * 8;
                float v0 = a[half * 2 + 0], v1 = a[half * 2 + 1];
                const size_t go = (size_t)r * DDIM + cg;
                if (EPI == 0) {
                    v0 = fmaxf(v0, 0.f); v1 = fmaxf(v1, 0.f);
                    uint32_t h, l; split2(v0, v1, h, l);
                    *(uint32_t*)((char*)OutH + 2 * go) = h;
                    *(uint32_t*)((char*)OutL + 2 * go) = l;
                } else if (EPI == 1) {
                    v0 = fmaxf(fmaf(v0, invv[cl], addv[cl]), 0.f);
                    v1 = fmaxf(fmaf(v1, invv[cl + 1], addv[cl + 1]), 0.f);
                    uint32_t h, l; split2(v0, v1, h, l);
                    *(uint32_t*)((char*)OutH + 2 * go) = h;
                    *(uint32_t*)((char*)OutL + 2 * go) = l;
                } else if (EPI == 2) {
                    float2 o;
                    o.x = fmaxf(fmaf(v0, invv[cl], addv[cl]), 0.f);
                    o.y = fmaxf(fmaf(v1, invv[cl + 1], addv[cl + 1]), 0.f);
                    *(float2*)(OutF + go) = o;
                } else {
                    const uint32_t hh = *(const uint32_t*)((const char*)Ph + 2 * go);
                    const uint32_t ll = *(const uint32_t*)((const char*)Pl + 2 * go);
                    const float2 vv = *(const float2*)(Vf + go);
                    const float p0 = bflo(hh) + bflo(ll);
                    const float p1 = bfhi(hh) + bfhi(ll);
                    const float s0v = 1.f / (1.f + __expf(-v0));
                    const float s1v = 1.f / (1.f + __expf(-v1));
                    float2 o;
                    o.x = fmaf(p0, s0v, vv.x);
                    o.y = fmaf(p1, s1v, vv.y);
                    *(float2*)(OutF + go) = o;
                }
            }
        }
    }
}

// ---------------- launch (stream-fork: G1 || G2->G3, join, G4) ----------------
extern "C" void kernel_launch(void* const* d_in, const int* in_sizes, int n_in,
                              void* d_out, int out_size)
{
    const float* F1   = (const float*)d_in[0];
    const float* F2   = (const float*)d_in[1];
    const float* Wk   = (const float*)d_in[2];
    const float* Wv1  = (const float*)d_in[3];
    const float* Wv2  = (const float*)d_in[4];
    const float* bn1g = (const float*)d_in[5];
    const float* bn1b = (const float*)d_in[6];
    const float* bn1m = (const float*)d_in[7];
    const float* bn1v = (const float*)d_in[8];
    const float* bn2g = (const float*)d_in[9];
    const float* bn2b = (const float*)d_in[10];
    const float* bn2m = (const float*)d_in[11];
    const float* bn2v = (const float*)d_in[12];
    // d_in[13]=Wa, d_in[14]=Wqk unused: softmax over identical L-columns is uniform 1/L.
    const float* Wvc  = (const float*)d_in[15];
    float* out = (float*)d_out;

    __nv_bfloat16 *Ph, *Pl, *Hh, *Hl, *Wh, *Wl;
    float* V;
    cudaGetSymbolAddress((void**)&Ph, g_Ph);
    cudaGetSymbolAddress((void**)&Pl, g_Pl);
    cudaGetSymbolAddress((void**)&Hh, g_Hh);
    cudaGetSymbolAddress((void**)&Hl, g_Hl);
    cudaGetSymbolAddress((void**)&V,  g_V);
    cudaGetSymbolAddress((void**)&Wh, g_Wh);
    cudaGetSymbolAddress((void**)&Wl, g_Wl);
    const int WSZ = 512 * 512;

    cudaFuncSetAttribute(gemm_hmma<0,0>, cudaFuncAttributeMaxDynamicSharedMemorySize, SM_TOTAL);
    cudaFuncSetAttribute(gemm_hmma<0,1>, cudaFuncAttributeMaxDynamicSharedMemorySize, SM_TOTAL);
    cudaFuncSetAttribute(gemm_hmma<1,2>, cudaFuncAttributeMaxDynamicSharedMemorySize, SM_TOTAL);
    cudaFuncSetAttribute(gemm_hmma<1,3>, cudaFuncAttributeMaxDynamicSharedMemorySize, SM_TOTAL);

    // stream/event resources: created once on the first (uncaptured correctness) call,
    // reused identically on every call -> deterministic work, capture-legal fork/join
    static cudaStream_t s2 = nullptr;
    static cudaEvent_t evW = nullptr, ev3 = nullptr;
    if (!s2) {
        cudaStreamCreateWithFlags(&s2, cudaStreamNonBlocking);
        cudaEventCreateWithFlags(&evW, cudaEventDisableTiming);
        cudaEventCreateWithFlags(&ev3, cudaEventDisableTiming);
    }

    dim3 grid(DDIM / BN, NROWS / BM);   // (4, 512)
    dim3 block(NTH);

    // weight hi/lo split: mat0=Wk, mat1=Wv1, mat2=Wv2, mat3=Wvc
    split_weights<<<4096, 256>>>(Wk, Wv1, Wv2, Wvc);
    cudaEventRecord(evW, 0);
    cudaStreamWaitEvent(s2, evW, 0);

    // G1 (default stream): P(hi/lo) = split(relu(F1 @ Wk^T))
    gemm_hmma<0,0><<<grid, block, SM_TOTAL>>>(F1, nullptr, nullptr, Wh + 0 * WSZ, Wl + 0 * WSZ,
        nullptr, Ph, Pl, nullptr, nullptr, nullptr, nullptr, nullptr, nullptr, nullptr);

    // G2 (s2): H(hi/lo) = split(relu(bn1(F2 @ Wv1^T)))
    gemm_hmma<0,1><<<grid, block, SM_TOTAL, s2>>>(F2, nullptr, nullptr, Wh + 1 * WSZ, Wl + 1 * WSZ,
        nullptr, Hh, Hl, bn1g, bn1b, bn1m, bn1v, nullptr, nullptr, nullptr);
    // G3 (s2, after G2): V = relu(bn2(H @ Wv2^T))
    gemm_hmma<1,2><<<grid, block, SM_TOTAL, s2>>>(nullptr, Hh, Hl, Wh + 2 * WSZ, Wl + 2 * WSZ,
        V, nullptr, nullptr, bn2g, bn2b, bn2m, bn2v, nullptr, nullptr, nullptr);
    cudaEventRecord(ev3, s2);

    // join: G4 needs P (G1, default stream) and V (G3, s2)
    cudaStreamWaitEvent(0, ev3, 0);
    // G4: out = V + P * sigmoid(P @ Wvc^T)
    gemm_hmma<1,3><<<grid, block, SM_TOTAL>>>(nullptr, Ph, Pl, Wh + 3 * WSZ, Wl + 3 * WSZ,
        out, nullptr, nullptr, nullptr, nullptr, nullptr, nullptr, Ph, Pl, V);
}

// round 14
// speedup vs baseline: 3.7836x; 1.3780x over previous
#include <cuda_runtime.h>
#include <cuda_fp16.h>
#include <cstdint>

#define NROWS 65536
#define KDIM  512
#define DDIM  512

// ---------------- device scratch (allocation-free) ----------------
__device__ __half g_P[(size_t)NROWS * DDIM];    // P  (single fp16)
__device__ __half g_H[(size_t)NROWS * DDIM];    // H  (single fp16)
__device__ float  g_V[(size_t)NROWS * DDIM];
__device__ __half g_Wh[4][512 * 512];           // weight hi (fp16)
__device__ __half g_Wl[4][512 * 512];           // weight lo (fp16 residual)

// ---------------- PTX helpers (baseline sm_80+, no 'a'-arch features) ----------------
__device__ __forceinline__ uint32_t smem_u32(const void* p) {
    uint32_t a;
    asm("{ .reg .u64 t; cvta.to.shared.u64 t, %1; cvt.u32.u64 %0, t; }" : "=r"(a) : "l"(p));
    return a;
}
__device__ __forceinline__ void ldsm4(uint32_t& r0, uint32_t& r1, uint32_t& r2, uint32_t& r3,
                                      uint32_t addr) {
    asm volatile("ldmatrix.sync.aligned.m8n8.x4.shared.b16 {%0,%1,%2,%3}, [%4];"
                 : "=r"(r0), "=r"(r1), "=r"(r2), "=r"(r3) : "r"(addr));
}
__device__ __forceinline__ void mma_f16(float* c, const uint32_t* a, const uint32_t* b) {
    asm volatile("mma.sync.aligned.m16n8k16.row.col.f32.f16.f16.f32 "
                 "{%0,%1,%2,%3}, {%4,%5,%6,%7}, {%8,%9}, {%0,%1,%2,%3};"
                 : "+f"(c[0]), "+f"(c[1]), "+f"(c[2]), "+f"(c[3])
                 : "r"(a[0]), "r"(a[1]), "r"(a[2]), "r"(a[3]), "r"(b[0]), "r"(b[1]));
}
#define CPA16(dst, src)  asm volatile("cp.async.cg.shared.global [%0], [%1], 16;" :: "r"(dst), "l"(src) : "memory")
#define CPA_COMMIT()     asm volatile("cp.async.commit_group;" ::: "memory")
#define CPA_WAIT1()      asm volatile("cp.async.wait_group 1;" ::: "memory")
#define CPA_WAIT0()      asm volatile("cp.async.wait_group 0;" ::: "memory")

// pack two floats to f16x2 (low half = a)
__device__ __forceinline__ uint32_t pack_h2(float a, float b) {
    uint32_t r;
    asm("cvt.rn.f16x2.f32 %0, %1, %2;" : "=r"(r) : "f"(b), "f"(a));
    return r;
}

// ---------------- layout constants ----------------
constexpr int BM = 128, BN = 128, KC = 32, KT = KDIM / KC;   // 16 k-chunks
constexpr int NTH = 256;
constexpr int NSTAGE = 3;
// 64B rows (32 fp16), XOR swizzle on 16B quads: q' = q ^ ((row>>1)&3)  (verified).
constexpr int OPB = 128 * 64;               // 8192 per operand buffer
constexpr int OFF_A = 0, OFF_BHI = OPB, OFF_BLO = 2 * OPB;
constexpr int STAGE_BYTES = 3 * OPB;        // 24576
constexpr int SM_STAGE = 1024;              // bn coeffs live in [0,1024)
constexpr int SM_TOTAL = SM_STAGE + NSTAGE * STAGE_BYTES;   // 74752 -> 2 CTAs/SM

__device__ __forceinline__ uint32_t swq(int row, int q) {
    return (uint32_t)((row << 6) + ((q ^ ((row >> 1) & 3)) << 4));
}

// ---------------- weight split prep (fp16 hi/lo) ----------------
__global__ void split_weights(const float* __restrict__ w0, const float* __restrict__ w1,
                              const float* __restrict__ w2, const float* __restrict__ w3) {
    int idx = blockIdx.x * blockDim.x + threadIdx.x;
    int mat = idx >> 18;
    int off = idx & 0x3FFFF;
    const float* s = (mat == 0) ? w0 : (mat == 1) ? w1 : (mat == 2) ? w2 : w3;
    float x = s[off];
    __half h = __float2half_rn(x);
    g_Wh[mat][off] = h;
    g_Wl[mat][off] = __float2half_rn(x - __half2float(h));
}

// ---------------- split-fp16 HMMA GEMM (2-product), 3-stage 1-sync, 2 CTAs/SM ----------------
// D[n,d] = epi( sum_k A[n,k] * B[d,k] ),  B = Bh + Bl (fp16 split), A single fp16
// AMODE 0: A fp32 (convert to fp16 in-kernel)   AMODE 1: A native fp16 (exact)
// EPI 0: relu -> OutHalf      EPI 1: relu(bn) -> OutHalf
// EPI 2: relu(bn) -> OutF     EPI 3: OutF = Vf + P*sigmoid(acc)   (P from Ph fp16)
template <int AMODE, int EPI>
__global__ __launch_bounds__(NTH, 2)
void gemm_hmma(const float* __restrict__ Af,
               const __half* __restrict__ Ah,
               const __half* __restrict__ Bh, const __half* __restrict__ Bl,
               float* __restrict__ OutF, __half* __restrict__ OutHalf,
               const float* __restrict__ bng, const float* __restrict__ bnb,
               const float* __restrict__ bnm, const float* __restrict__ bnv,
               const __half* __restrict__ Ph, const float* __restrict__ Vf)
{
    extern __shared__ char smem[];
    const uint32_t sb = smem_u32(smem);
    const int tid = threadIdx.x;
    const int wid = tid >> 5, lid = tid & 31;
    const int bxc = blockIdx.x * BN;
    const int bym = blockIdx.y * BM;
    const int wm = (wid >> 2) * 64;     // warp m-band
    const int wn = (wid & 3) * 32;      // warp n-band

    if ((EPI == 1 || EPI == 2) && tid < 128) {
        int c = bxc + tid;
        float iv = bng[c] * rsqrtf(bnv[c] + 1e-5f);
        ((float*)smem)[tid]         = iv;
        ((float*)(smem + 512))[tid] = bnb[c] - bnm[c] * iv;
    }

    // lane row/quad decomposition for ldsm
    const int aRow = lid & 15;                       // + wm + mf*16
    const int aQ   = lid >> 4;                       // + 2*ks
    const int bRow = (lid & 7) + ((lid >> 4) << 3);  // + wn + p*16
    const int bQ   = (lid & 8) >> 3;                 // + 2*ks

    // ---- load issue helpers ----
    auto issueB = [&](int kt, uint32_t stu) {
#pragma unroll
        for (int i = 0; i < 2; i++) {
            int q = tid + i * NTH;                 // 512 16B quads per half
            int row = q >> 2, kc = q & 3;
            size_t e = (size_t)(bxc + row) * KDIM + kt * KC + kc * 8;
            uint32_t d = swq(row, kc);
            CPA16(stu + OFF_BHI + d, (const char*)Bh + 2 * e);
            CPA16(stu + OFF_BLO + d, (const char*)Bl + 2 * e);
        }
    };
    auto issueA1 = [&](int kt, uint32_t stu) {
#pragma unroll
        for (int i = 0; i < 2; i++) {
            int q = tid + i * NTH;                 // 512 16B quads
            int row = q >> 2, kc = q & 3;
            size_t e = (size_t)(bym + row) * KDIM + kt * KC + kc * 8;
            CPA16(stu + OFF_A + swq(row, kc), (const char*)Ah + 2 * e);
        }
    };
    auto ldA0 = [&](int kt, float4* aReg) {
#pragma unroll
        for (int i = 0; i < 4; i++) {
            int f = tid + i * NTH;                 // 1024 float4 slots (128 rows x 8)
            int row = f >> 3, kq = f & 7;
            aReg[i] = *(const float4*)(Af + (size_t)(bym + row) * KDIM + kt * KC + kq * 4);
        }
    };
    auto stsA0 = [&](char* st, const float4* aReg) {
#pragma unroll
        for (int i = 0; i < 4; i++) {
            int f = tid + i * NTH;
            int row = f >> 3, kq = f & 7;          // 8B units
            uint32_t h01 = pack_h2(aReg[i].x, aReg[i].y);
            uint32_t h23 = pack_h2(aReg[i].z, aReg[i].w);
            uint32_t d = swq(row, kq >> 1) + (kq & 1) * 8;
            *(uint2*)(st + OFF_A + d) = make_uint2(h01, h23);
        }
    };

    // ---- accumulators ----
    float acc[4][4][4];
#pragma unroll
    for (int mf = 0; mf < 4; mf++)
#pragma unroll
        for (int j = 0; j < 4; j++)
#pragma unroll
            for (int e = 0; e < 4; e++) acc[mf][j][e] = 0.f;

    // one k16-step: 8 ldsm4 + 32 MMA (A single, B hi+lo)
    auto computeKS = [&](int ks, uint32_t s0) {
        uint32_t bh[4][2], bl[4][2], af[4][4];
#pragma unroll
        for (int p = 0; p < 2; p++) {
            int row = wn + p * 16 + bRow;
            uint32_t ad = s0 + swq(row, 2 * ks + bQ);
            ldsm4(bh[2*p][0], bh[2*p][1], bh[2*p+1][0], bh[2*p+1][1], ad + OFF_BHI);
            ldsm4(bl[2*p][0], bl[2*p][1], bl[2*p+1][0], bl[2*p+1][1], ad + OFF_BLO);
        }
#pragma unroll
        for (int mf = 0; mf < 4; mf++) {
            int row = wm + mf * 16 + aRow;
            ldsm4(af[mf][0], af[mf][1], af[mf][2], af[mf][3],
                  s0 + OFF_A + swq(row, 2 * ks + aQ));
        }
#pragma unroll
        for (int mf = 0; mf < 4; mf++)
#pragma unroll
            for (int j = 0; j < 4; j++) mma_f16(acc[mf][j], af[mf], bh[j]);
#pragma unroll
        for (int mf = 0; mf < 4; mf++)
#pragma unroll
            for (int j = 0; j < 4; j++) mma_f16(acc[mf][j], af[mf], bl[j]);
    };

    // ---- prologue: fill stages 0 and 1 ----
#pragma unroll
    for (int pk = 0; pk < NSTAGE - 1; pk++) {
        char* st = smem + SM_STAGE + pk * STAGE_BYTES;
        uint32_t stu = sb + SM_STAGE + pk * STAGE_BYTES;
        if (AMODE == 0) {
            float4 aR[4];
            ldA0(pk, aR);
            stsA0(st, aR);
        } else {
            issueA1(pk, stu);
        }
        issueB(pk, stu);
        CPA_COMMIT();
    }

    // ---- mainloop (R13-verified order; refill placement differs by AMODE) ----
    float4 aReg[4];
    for (int kt = 0; kt < KT; kt++) {
        const int s = kt % NSTAGE;
        const uint32_t s0 = sb + SM_STAGE + s * STAGE_BYTES;
        const int kpre = kt + NSTAGE - 1;

        if (AMODE == 0 && kpre < KT) ldA0(kpre, aReg);   // hoisted LDG above the wait

        CPA_WAIT1();           // groups through chunk kt complete
        __syncthreads();       // chunk kt visible to all; stage (kt-1)%3 free

        if (AMODE == 0) {
            if (kpre < KT) {
                const int slot = kpre % NSTAGE;
                stsA0(smem + SM_STAGE + slot * STAGE_BYTES, aReg);
                issueB(kpre, sb + SM_STAGE + slot * STAGE_BYTES);
            }
            CPA_COMMIT();
            computeKS(0, s0);
            computeKS(1, s0);
        } else {
            // deferred refill: cp.async burst rides under ks=1's MMA shadow
            computeKS(0, s0);
            if (kpre < KT) {
                const int slot = kpre % NSTAGE;
                uint32_t stu = sb + SM_STAGE + slot * STAGE_BYTES;
                issueA1(kpre, stu);
                issueB(kpre, stu);
            }
            CPA_COMMIT();
            computeKS(1, s0);
        }
    }
    CPA_WAIT0();

    // ---- epilogue: fragments -> global ----
    const float* invv = (const float*)smem;
    const float* addv = (const float*)(smem + 512);
#pragma unroll
    for (int mf = 0; mf < 4; mf++) {
#pragma unroll
        for (int j = 0; j < 4; j++) {
            const float* a = acc[mf][j];
            const int rg = bym + wm + mf * 16 + (lid >> 2);
            const int cl = wn + j * 8 + (lid & 3) * 2;
            const int cg = bxc + cl;
#pragma unroll
            for (int half = 0; half < 2; half++) {
                const int r = rg + half * 8;
                float v0 = a[half * 2 + 0], v1 = a[half * 2 + 1];
                const size_t go = (size_t)r * DDIM + cg;
                if (EPI == 0) {
                    v0 = fmaxf(v0, 0.f); v1 = fmaxf(v1, 0.f);
                    *(uint32_t*)((char*)OutHalf + 2 * go) = pack_h2(v0, v1);
                } else if (EPI == 1) {
                    v0 = fmaxf(fmaf(v0, invv[cl], addv[cl]), 0.f);
                    v1 = fmaxf(fmaf(v1, invv[cl + 1], addv[cl + 1]), 0.f);
                    *(uint32_t*)((char*)OutHalf + 2 * go) = pack_h2(v0, v1);
                } else if (EPI == 2) {
                    float2 o;
                    o.x = fmaxf(fmaf(v0, invv[cl], addv[cl]), 0.f);
                    o.y = fmaxf(fmaf(v1, invv[cl + 1], addv[cl + 1]), 0.f);
                    *(float2*)(OutF + go) = o;
                } else {
                    const __half2 pv = *(const __half2*)((const char*)Ph + 2 * go);
                    const float2 vv = *(const float2*)(Vf + go);
                    const float p0 = __half2float(__low2half(pv));
                    const float p1 = __half2float(__high2half(pv));
                    const float s0v = 1.f / (1.f + __expf(-v0));
                    const float s1v = 1.f / (1.f + __expf(-v1));
                    float2 o;
                    o.x = fmaf(p0, s0v, vv.x);
                    o.y = fmaf(p1, s1v, vv.y);
                    *(float2*)(OutF + go) = o;
                }
            }
        }
    }
}

// ---------------- launch (stream-fork: G1 || G2->G3, join, G4) ----------------
extern "C" void kernel_launch(void* const* d_in, const int* in_sizes, int n_in,
                              void* d_out, int out_size)
{
    const float* F1   = (const float*)d_in[0];
    const float* F2   = (const float*)d_in[1];
    const float* Wk   = (const float*)d_in[2];
    const float* Wv1  = (const float*)d_in[3];
    const float* Wv2  = (const float*)d_in[4];
    const float* bn1g = (const float*)d_in[5];
    const float* bn1b = (const float*)d_in[6];
    const float* bn1m = (const float*)d_in[7];
    const float* bn1v = (const float*)d_in[8];
    const float* bn2g = (const float*)d_in[9];
    const float* bn2b = (const float*)d_in[10];
    const float* bn2m = (const float*)d_in[11];
    const float* bn2v = (const float*)d_in[12];
    // d_in[13]=Wa, d_in[14]=Wqk unused: softmax over identical L-columns is uniform 1/L.
    const float* Wvc  = (const float*)d_in[15];
    float* out = (float*)d_out;

    __half *P, *H, *Wh, *Wl;
    float* V;
    cudaGetSymbolAddress((void**)&P,  g_P);
    cudaGetSymbolAddress((void**)&H,  g_H);
    cudaGetSymbolAddress((void**)&V,  g_V);
    cudaGetSymbolAddress((void**)&Wh, g_Wh);
    cudaGetSymbolAddress((void**)&Wl, g_Wl);
    const int WSZ = 512 * 512;

    cudaFuncSetAttribute(gemm_hmma<0,0>, cudaFuncAttributeMaxDynamicSharedMemorySize, SM_TOTAL);
    cudaFuncSetAttribute(gemm_hmma<0,1>, cudaFuncAttributeMaxDynamicSharedMemorySize, SM_TOTAL);
    cudaFuncSetAttribute(gemm_hmma<1,2>, cudaFuncAttributeMaxDynamicSharedMemorySize, SM_TOTAL);
    cudaFuncSetAttribute(gemm_hmma<1,3>, cudaFuncAttributeMaxDynamicSharedMemorySize, SM_TOTAL);

    // stream/event resources: created once on the first (uncaptured correctness) call,
    // reused identically on every call -> deterministic, capture-legal fork/join
    static cudaStream_t s2 = nullptr;
    static cudaEvent_t evW = nullptr, ev3 = nullptr;
    if (!s2) {
        cudaStreamCreateWithFlags(&s2, cudaStreamNonBlocking);
        cudaEventCreateWithFlags(&evW, cudaEventDisableTiming);
        cudaEventCreateWithFlags(&ev3, cudaEventDisableTiming);
    }

    dim3 grid(DDIM / BN, NROWS / BM);   // (4, 512)
    dim3 block(NTH);

    // weight hi/lo split: mat0=Wk, mat1=Wv1, mat2=Wv2, mat3=Wvc
    split_weights<<<4096, 256>>>(Wk, Wv1, Wv2, Wvc);
    cudaEventRecord(evW, 0);
    cudaStreamWaitEvent(s2, evW, 0);

    // G1 (default stream): P = fp16(relu(F1 @ Wk^T))
    gemm_hmma<0,0><<<grid, block, SM_TOTAL>>>(F1, nullptr, Wh + 0 * WSZ, Wl + 0 * WSZ,
        nullptr, P, nullptr, nullptr, nullptr, nullptr, nullptr, nullptr);

    // G2 (s2): H = fp16(relu(bn1(F2 @ Wv1^T)))
    gemm_hmma<0,1><<<grid, block, SM_TOTAL, s2>>>(F2, nullptr, Wh + 1 * WSZ, Wl + 1 * WSZ,
        nullptr, H, bn1g, bn1b, bn1m, bn1v, nullptr, nullptr);
    // G3 (s2, after G2): V = relu(bn2(H @ Wv2^T))   (A = native fp16, exact)
    gemm_hmma<1,2><<<grid, block, SM_TOTAL, s2>>>(nullptr, H, Wh + 2 * WSZ, Wl + 2 * WSZ,
        V, nullptr, bn2g, bn2b, bn2m, bn2v, nullptr, nullptr);
    cudaEventRecord(ev3, s2);

    // join: G4 needs P (G1, default stream) and V (G3, s2)
    cudaStreamWaitEvent(0, ev3, 0);
    // G4: out = V + P * sigmoid(P @ Wvc^T)
    gemm_hmma<1,3><<<grid, block, SM_TOTAL>>>(nullptr, P, Wh + 3 * WSZ, Wl + 3 * WSZ,
        out, nullptr, nullptr, nullptr, nullptr, nullptr, P, V);
}

// round 15
// speedup vs baseline: 5.1197x; 1.3531x over previous
#include <cuda_runtime.h>
#include <cuda_fp16.h>
#include <cstdint>

#define NROWS 65536
#define KDIM  512
#define DDIM  512

// ---------------- device scratch (allocation-free) ----------------
__device__ __half g_P[(size_t)NROWS * DDIM];    // P  (fp16)
__device__ __half g_H[(size_t)NROWS * DDIM];    // H  (fp16)
__device__ float  g_V[(size_t)NROWS * DDIM];
__device__ __half g_W[4][512 * 512];            // weights (fp16)

// ---------------- PTX helpers (baseline sm_80+, no 'a'-arch features) ----------------
__device__ __forceinline__ uint32_t smem_u32(const void* p) {
    uint32_t a;
    asm("{ .reg .u64 t; cvta.to.shared.u64 t, %1; cvt.u32.u64 %0, t; }" : "=r"(a) : "l"(p));
    return a;
}
__device__ __forceinline__ void ldsm4(uint32_t& r0, uint32_t& r1, uint32_t& r2, uint32_t& r3,
                                      uint32_t addr) {
    asm volatile("ldmatrix.sync.aligned.m8n8.x4.shared.b16 {%0,%1,%2,%3}, [%4];"
                 : "=r"(r0), "=r"(r1), "=r"(r2), "=r"(r3) : "r"(addr));
}
__device__ __forceinline__ void mma_f16(float* c, const uint32_t* a, const uint32_t* b) {
    asm volatile("mma.sync.aligned.m16n8k16.row.col.f32.f16.f16.f32 "
                 "{%0,%1,%2,%3}, {%4,%5,%6,%7}, {%8,%9}, {%0,%1,%2,%3};"
                 : "+f"(c[0]), "+f"(c[1]), "+f"(c[2]), "+f"(c[3])
                 : "r"(a[0]), "r"(a[1]), "r"(a[2]), "r"(a[3]), "r"(b[0]), "r"(b[1]));
}
#define CPA16(dst, src)  asm volatile("cp.async.cg.shared.global [%0], [%1], 16;" :: "r"(dst), "l"(src) : "memory")
#define CPA_COMMIT()     asm volatile("cp.async.commit_group;" ::: "memory")
#define CPA_WAIT1()      asm volatile("cp.async.wait_group 1;" ::: "memory")
#define CPA_WAIT0()      asm volatile("cp.async.wait_group 0;" ::: "memory")

// pack two floats to f16x2 (low half = a)
__device__ __forceinline__ uint32_t pack_h2(float a, float b) {
    uint32_t r;
    asm("cvt.rn.f16x2.f32 %0, %1, %2;" : "=r"(r) : "f"(b), "f"(a));
    return r;
}

// ---------------- layout constants ----------------
constexpr int BM = 128, BN = 128, KC = 32, KT = KDIM / KC;   // 16 k-chunks
constexpr int NTH = 256;
constexpr int NSTAGE = 3;
// 64B rows (32 fp16), XOR swizzle on 16B quads: q' = q ^ ((row>>1)&3)  (verified).
constexpr int OPB = 128 * 64;               // 8192 per operand buffer
constexpr int OFF_A = 0, OFF_B = OPB;
constexpr int STAGE_BYTES = 2 * OPB;        // 16384
constexpr int SM_STAGE = 1024;              // bn coeffs live in [0,1024)
constexpr int SM_TOTAL = SM_STAGE + NSTAGE * STAGE_BYTES;   // 50176 -> 2 CTAs/SM

__device__ __forceinline__ uint32_t swq(int row, int q) {
    return (uint32_t)((row << 6) + ((q ^ ((row >> 1) & 3)) << 4));
}

// ---------------- weight fp16 convert ----------------
__global__ void conv_weights(const float* __restrict__ w0, const float* __restrict__ w1,
                             const float* __restrict__ w2, const float* __restrict__ w3) {
    int idx = blockIdx.x * blockDim.x + threadIdx.x;
    int mat = idx >> 18;
    int off = idx & 0x3FFFF;
    const float* s = (mat == 0) ? w0 : (mat == 1) ? w1 : (mat == 2) ? w2 : w3;
    g_W[mat][off] = __float2half_rn(s[off]);
}

// ---------------- fp16 HMMA GEMM, 3-stage 1-sync pipeline, 2 CTAs/SM ----------------
// D[n,d] = epi( sum_k A[n,k] * B[d,k] ),  A,B fp16, fp32 accum
// AMODE 0: A fp32 (convert to fp16 in-kernel)   AMODE 1: A native fp16
// EPI 0: relu -> OutHalf      EPI 1: relu(bn) -> OutHalf
// EPI 2: relu(bn) -> OutF     EPI 3: OutF = Vf + P*sigmoid(acc)
template <int AMODE, int EPI>
__global__ __launch_bounds__(NTH, 2)
void gemm_hmma(const float* __restrict__ Af,
               const __half* __restrict__ Ah,
               const __half* __restrict__ Bw,
               float* __restrict__ OutF, __half* __restrict__ OutHalf,
               const float* __restrict__ bng, const float* __restrict__ bnb,
               const float* __restrict__ bnm, const float* __restrict__ bnv,
               const __half* __restrict__ Ph, const float* __restrict__ Vf)
{
    extern __shared__ char smem[];
    const uint32_t sb = smem_u32(smem);
    const int tid = threadIdx.x;
    const int wid = tid >> 5, lid = tid & 31;
    const int bxc = blockIdx.x * BN;
    const int bym = blockIdx.y * BM;
    const int wm = (wid >> 2) * 64;     // warp m-band
    const int wn = (wid & 3) * 32;      // warp n-band

    if ((EPI == 1 || EPI == 2) && tid < 128) {
        int c = bxc + tid;
        float iv = bng[c] * rsqrtf(bnv[c] + 1e-5f);
        ((float*)smem)[tid]         = iv;
        ((float*)(smem + 512))[tid] = bnb[c] - bnm[c] * iv;
    }

    // lane row/quad decomposition for ldsm
    const int aRow = lid & 15;                       // + wm + mf*16
    const int aQ   = lid >> 4;                       // + 2*ks
    const int bRow = (lid & 7) + ((lid >> 4) << 3);  // + wn + p*16
    const int bQ   = (lid & 8) >> 3;                 // + 2*ks

    // ---- load issue helpers ----
    auto issueB = [&](int kt, uint32_t stu) {
#pragma unroll
        for (int i = 0; i < 2; i++) {
            int q = tid + i * NTH;                 // 512 16B quads
            int row = q >> 2, kc = q & 3;
            size_t e = (size_t)(bxc + row) * KDIM + kt * KC + kc * 8;
            CPA16(stu + OFF_B + swq(row, kc), (const char*)Bw + 2 * e);
        }
    };
    auto issueA1 = [&](int kt, uint32_t stu) {
#pragma unroll
        for (int i = 0; i < 2; i++) {
            int q = tid + i * NTH;                 // 512 16B quads
            int row = q >> 2, kc = q & 3;
            size_t e = (size_t)(bym + row) * KDIM + kt * KC + kc * 8;
            CPA16(stu + OFF_A + swq(row, kc), (const char*)Ah + 2 * e);
        }
    };
    auto ldA0 = [&](int kt, float4* aReg) {
#pragma unroll
        for (int i = 0; i < 4; i++) {
            int f = tid + i * NTH;                 // 1024 float4 slots (128 rows x 8)
            int row = f >> 3, kq = f & 7;
            aReg[i] = *(const float4*)(Af + (size_t)(bym + row) * KDIM + kt * KC + kq * 4);
        }
    };
    auto stsA0 = [&](char* st, const float4* aReg) {
#pragma unroll
        for (int i = 0; i < 4; i++) {
            int f = tid + i * NTH;
            int row = f >> 3, kq = f & 7;          // 8B units
            uint32_t h01 = pack_h2(aReg[i].x, aReg[i].y);
            uint32_t h23 = pack_h2(aReg[i].z, aReg[i].w);
            uint32_t d = swq(row, kq >> 1) + (kq & 1) * 8;
            *(uint2*)(st + OFF_A + d) = make_uint2(h01, h23);
        }
    };

    // ---- accumulators ----
    float acc[4][4][4];
#pragma unroll
    for (int mf = 0; mf < 4; mf++)
#pragma unroll
        for (int j = 0; j < 4; j++)
#pragma unroll
            for (int e = 0; e < 4; e++) acc[mf][j][e] = 0.f;

    // one k16-step: 6 ldsm4 + 16 MMA
    auto computeKS = [&](int ks, uint32_t s0) {
        uint32_t bf[4][2], af[4][4];
#pragma unroll
        for (int p = 0; p < 2; p++) {
            int row = wn + p * 16 + bRow;
            ldsm4(bf[2*p][0], bf[2*p][1], bf[2*p+1][0], bf[2*p+1][1],
                  s0 + OFF_B + swq(row, 2 * ks + bQ));
        }
#pragma unroll
        for (int mf = 0; mf < 4; mf++) {
            int row = wm + mf * 16 + aRow;
            ldsm4(af[mf][0], af[mf][1], af[mf][2], af[mf][3],
                  s0 + OFF_A + swq(row, 2 * ks + aQ));
        }
#pragma unroll
        for (int mf = 0; mf < 4; mf++)
#pragma unroll
            for (int j = 0; j < 4; j++) mma_f16(acc[mf][j], af[mf], bf[j]);
    };

    // ---- prologue: fill stages 0 and 1 ----
#pragma unroll
    for (int pk = 0; pk < NSTAGE - 1; pk++) {
        char* st = smem + SM_STAGE + pk * STAGE_BYTES;
        uint32_t stu = sb + SM_STAGE + pk * STAGE_BYTES;
        if (AMODE == 0) {
            float4 aR[4];
            ldA0(pk, aR);
            stsA0(st, aR);
        } else {
            issueA1(pk, stu);
        }
        issueB(pk, stu);
        CPA_COMMIT();
    }

    // ---- mainloop (R13/R14-verified order; refill placement differs by AMODE) ----
    float4 aReg[4];
    for (int kt = 0; kt < KT; kt++) {
        const int s = kt % NSTAGE;
        const uint32_t s0 = sb + SM_STAGE + s * STAGE_BYTES;
        const int kpre = kt + NSTAGE - 1;

        if (AMODE == 0 && kpre < KT) ldA0(kpre, aReg);   // hoisted LDG above the wait

        CPA_WAIT1();           // groups through chunk kt complete
        __syncthreads();       // chunk kt visible to all; stage (kt-1)%3 free

        if (AMODE == 0) {
            if (kpre < KT) {
                const int slot = kpre % NSTAGE;
                stsA0(smem + SM_STAGE + slot * STAGE_BYTES, aReg);
                issueB(kpre, sb + SM_STAGE + slot * STAGE_BYTES);
            }
            CPA_COMMIT();
            computeKS(0, s0);
            computeKS(1, s0);
        } else {
            // deferred refill: cp.async burst rides under ks=1's MMA shadow
            computeKS(0, s0);
            if (kpre < KT) {
                const int slot = kpre % NSTAGE;
                uint32_t stu = sb + SM_STAGE + slot * STAGE_BYTES;
                issueA1(kpre, stu);
                issueB(kpre, stu);
            }
            CPA_COMMIT();
            computeKS(1, s0);
        }
    }
    CPA_WAIT0();

    // ---- epilogue: fragments -> global ----
    const float* invv = (const float*)smem;
    const float* addv = (const float*)(smem + 512);
#pragma unroll
    for (int mf = 0; mf < 4; mf++) {
#pragma unroll
        for (int j = 0; j < 4; j++) {
            const float* a = acc[mf][j];
            const int rg = bym + wm + mf * 16 + (lid >> 2);
            const int cl = wn + j * 8 + (lid & 3) * 2;
            const int cg = bxc + cl;
#pragma unroll
            for (int half = 0; half < 2; half++) {
                const int r = rg + half * 8;
                float v0 = a[half * 2 + 0], v1 = a[half * 2 + 1];
                const size_t go = (size_t)r * DDIM + cg;
                if (EPI == 0) {
                    v0 = fmaxf(v0, 0.f); v1 = fmaxf(v1, 0.f);
                    *(uint32_t*)((char*)OutHalf + 2 * go) = pack_h2(v0, v1);
                } else if (EPI == 1) {
                    v0 = fmaxf(fmaf(v0, invv[cl], addv[cl]), 0.f);
                    v1 = fmaxf(fmaf(v1, invv[cl + 1], addv[cl + 1]), 0.f);
                    *(uint32_t*)((char*)OutHalf + 2 * go) = pack_h2(v0, v1);
                } else if (EPI == 2) {
                    float2 o;
                    o.x = fmaxf(fmaf(v0, invv[cl], addv[cl]), 0.f);
                    o.y = fmaxf(fmaf(v1, invv[cl + 1], addv[cl + 1]), 0.f);
                    *(float2*)(OutF + go) = o;
                } else {
                    const __half2 pv = *(const __half2*)((const char*)Ph + 2 * go);
                    const float2 vv = *(const float2*)(Vf + go);
                    const float p0 = __half2float(__low2half(pv));
                    const float p1 = __half2float(__high2half(pv));
                    const float s0v = 1.f / (1.f + __expf(-v0));
                    const float s1v = 1.f / (1.f + __expf(-v1));
                    float2 o;
                    o.x = fmaf(p0, s0v, vv.x);
                    o.y = fmaf(p1, s1v, vv.y);
                    *(float2*)(OutF + go) = o;
                }
            }
        }
    }
}

// ---------------- launch (stream-fork: G1 || G2->G3, join, G4) ----------------
extern "C" void kernel_launch(void* const* d_in, const int* in_sizes, int n_in,
                              void* d_out, int out_size)
{
    const float* F1   = (const float*)d_in[0];
    const float* F2   = (const float*)d_in[1];
    const float* Wk   = (const float*)d_in[2];
    const float* Wv1  = (const float*)d_in[3];
    const float* Wv2  = (const float*)d_in[4];
    const float* bn1g = (const float*)d_in[5];
    const float* bn1b = (const float*)d_in[6];
    const float* bn1m = (const float*)d_in[7];
    const float* bn1v = (const float*)d_in[8];
    const float* bn2g = (const float*)d_in[9];
    const float* bn2b = (const float*)d_in[10];
    const float* bn2m = (const float*)d_in[11];
    const float* bn2v = (const float*)d_in[12];
    // d_in[13]=Wa, d_in[14]=Wqk unused: softmax over identical L-columns is uniform 1/L.
    const float* Wvc  = (const float*)d_in[15];
    float* out = (float*)d_out;

    __half *P, *H, *W;
    float* V;
    cudaGetSymbolAddress((void**)&P, g_P);
    cudaGetSymbolAddress((void**)&H, g_H);
    cudaGetSymbolAddress((void**)&V, g_V);
    cudaGetSymbolAddress((void**)&W, g_W);
    const int WSZ = 512 * 512;

    cudaFuncSetAttribute(gemm_hmma<0,0>, cudaFuncAttributeMaxDynamicSharedMemorySize, SM_TOTAL);
    cudaFuncSetAttribute(gemm_hmma<0,1>, cudaFuncAttributeMaxDynamicSharedMemorySize, SM_TOTAL);
    cudaFuncSetAttribute(gemm_hmma<1,2>, cudaFuncAttributeMaxDynamicSharedMemorySize, SM_TOTAL);
    cudaFuncSetAttribute(gemm_hmma<1,3>, cudaFuncAttributeMaxDynamicSharedMemorySize, SM_TOTAL);

    // stream/event resources: created once on the first (uncaptured correctness) call,
    // reused identically on every call -> deterministic, capture-legal fork/join
    static cudaStream_t s2 = nullptr;
    static cudaEvent_t evW = nullptr, ev3 = nullptr;
    if (!s2) {
        cudaStreamCreateWithFlags(&s2, cudaStreamNonBlocking);
        cudaEventCreateWithFlags(&evW, cudaEventDisableTiming);
        cudaEventCreateWithFlags(&ev3, cudaEventDisableTiming);
    }

    dim3 grid(DDIM / BN, NROWS / BM);   // (4, 512)
    dim3 block(NTH);

    // weight fp16 convert: mat0=Wk, mat1=Wv1, mat2=Wv2, mat3=Wvc
    conv_weights<<<4096, 256>>>(Wk, Wv1, Wv2, Wvc);
    cudaEventRecord(evW, 0);
    cudaStreamWaitEvent(s2, evW, 0);

    // G1 (default stream): P = fp16(relu(F1 @ Wk^T))
    gemm_hmma<0,0><<<grid, block, SM_TOTAL>>>(F1, nullptr, W + 0 * WSZ,
        nullptr, P, nullptr, nullptr, nullptr, nullptr, nullptr, nullptr);

    // G2 (s2): H = fp16(relu(bn1(F2 @ Wv1^T)))
    gemm_hmma<0,1><<<grid, block, SM_TOTAL, s2>>>(F2, nullptr, W + 1 * WSZ,
        nullptr, H, bn1g, bn1b, bn1m, bn1v, nullptr, nullptr);
    // G3 (s2, after G2): V = relu(bn2(H @ Wv2^T))
    gemm_hmma<1,2><<<grid, block, SM_TOTAL, s2>>>(nullptr, H, W + 2 * WSZ,
        V, nullptr, bn2g, bn2b, bn2m, bn2v, nullptr, nullptr);
    cudaEventRecord(ev3, s2);

    // join: G4 needs P (G1, default stream) and V (G3, s2)
    cudaStreamWaitEvent(0, ev3, 0);
    // G4: out = V + P * sigmoid(P @ Wvc^T)
    gemm_hmma<1,3><<<grid, block, SM_TOTAL>>>(nullptr, P, W + 3 * WSZ,
        out, nullptr, nullptr, nullptr, nullptr, nullptr, P, V);
}

// round 16
// speedup vs baseline: 5.2286x; 1.0213x over previous
#include <cuda_runtime.h>
#include <cuda_fp16.h>
#include <cstdint>

#define NROWS 65536
#define KDIM  512
#define DDIM  512

// ---------------- device scratch (allocation-free) ----------------
__device__ __half g_P[(size_t)NROWS * DDIM];    // P  (fp16)
__device__ __half g_H[(size_t)NROWS * DDIM];    // H  (fp16)
__device__ float  g_V[(size_t)NROWS * DDIM];
__device__ __half g_W[4][512 * 512];            // weights (fp16)

// ---------------- PTX helpers (baseline sm_80+, no 'a'-arch features) ----------------
__device__ __forceinline__ uint32_t smem_u32(const void* p) {
    uint32_t a;
    asm("{ .reg .u64 t; cvta.to.shared.u64 t, %1; cvt.u32.u64 %0, t; }" : "=r"(a) : "l"(p));
    return a;
}
__device__ __forceinline__ void ldsm4(uint32_t& r0, uint32_t& r1, uint32_t& r2, uint32_t& r3,
                                      uint32_t addr) {
    asm volatile("ldmatrix.sync.aligned.m8n8.x4.shared.b16 {%0,%1,%2,%3}, [%4];"
                 : "=r"(r0), "=r"(r1), "=r"(r2), "=r"(r3) : "r"(addr));
}
__device__ __forceinline__ void mma_f16(float* c, const uint32_t* a, const uint32_t* b) {
    asm volatile("mma.sync.aligned.m16n8k16.row.col.f32.f16.f16.f32 "
                 "{%0,%1,%2,%3}, {%4,%5,%6,%7}, {%8,%9}, {%0,%1,%2,%3};"
                 : "+f"(c[0]), "+f"(c[1]), "+f"(c[2]), "+f"(c[3])
                 : "r"(a[0]), "r"(a[1]), "r"(a[2]), "r"(a[3]), "r"(b[0]), "r"(b[1]));
}
#define CPA16(dst, src)  asm volatile("cp.async.cg.shared.global [%0], [%1], 16;" :: "r"(dst), "l"(src) : "memory")
#define CPA_COMMIT()     asm volatile("cp.async.commit_group;" ::: "memory")
#define CPA_WAIT1()      asm volatile("cp.async.wait_group 1;" ::: "memory")
#define CPA_WAIT0()      asm volatile("cp.async.wait_group 0;" ::: "memory")

// pack two floats to f16x2 (low half = a)
__device__ __forceinline__ uint32_t pack_h2(float a, float b) {
    uint32_t r;
    asm("cvt.rn.f16x2.f32 %0, %1, %2;" : "=r"(r) : "f"(b), "f"(a));
    return r;
}

// ---------------- layout constants ----------------
constexpr int BM = 128, BN = 128, KC = 64, KT = KDIM / KC;   // 8 k-chunks
constexpr int NTH = 256;
constexpr int NSTAGE = 3;
// Each chunk stored as TWO 32-col blocks of 64B rows with the verified XOR swizzle:
// swq(row,q) = row*64 + (q ^ ((row>>1)&3))*16
constexpr int OPB = 128 * 64;               // 8192 = one 32-col block (128 rows)
constexpr int OFF_A = 0;                    // A: 2 blocks = 16384
constexpr int OFF_B = 2 * OPB;              // B: 2 blocks = 16384
constexpr int STAGE_BYTES = 4 * OPB;        // 32768
constexpr int SM_STAGE = 1024;              // bn coeffs live in [0,1024)
constexpr int SM_TOTAL = SM_STAGE + NSTAGE * STAGE_BYTES;   // 99328 -> 2 CTAs/SM

__device__ __forceinline__ uint32_t swq(int row, int q) {
    return (uint32_t)((row << 6) + ((q ^ ((row >> 1) & 3)) << 4));
}

// ---------------- weight fp16 convert ----------------
__global__ void conv_weights(const float* __restrict__ w0, const float* __restrict__ w1,
                             const float* __restrict__ w2, const float* __restrict__ w3) {
    int idx = blockIdx.x * blockDim.x + threadIdx.x;
    int mat = idx >> 18;
    int off = idx & 0x3FFFF;
    const float* s = (mat == 0) ? w0 : (mat == 1) ? w1 : (mat == 2) ? w2 : w3;
    g_W[mat][off] = __float2half_rn(s[off]);
}

// ---------------- fp16 HMMA GEMM, KC=64, 3-stage 1-sync, 2 CTAs/SM ----------------
// D[n,d] = epi( sum_k A[n,k] * B[d,k] ),  A,B fp16, fp32 accum
// AMODE 0: A fp32 (convert to fp16 in-kernel, phased halves)   AMODE 1: A native fp16
// EPI 0: relu -> OutHalf      EPI 1: relu(bn) -> OutHalf
// EPI 2: relu(bn) -> OutF     EPI 3: OutF = Vf + P*sigmoid(acc)
template <int AMODE, int EPI>
__global__ __launch_bounds__(NTH, 2)
void gemm_hmma(const float* __restrict__ Af,
               const __half* __restrict__ Ah,
               const __half* __restrict__ Bw,
               float* __restrict__ OutF, __half* __restrict__ OutHalf,
               const float* __restrict__ bng, const float* __restrict__ bnb,
               const float* __restrict__ bnm, const float* __restrict__ bnv,
               const __half* __restrict__ Ph, const float* __restrict__ Vf)
{
    extern __shared__ char smem[];
    const uint32_t sb = smem_u32(smem);
    const int tid = threadIdx.x;
    const int wid = tid >> 5, lid = tid & 31;
    const int bxc = blockIdx.x * BN;
    const int bym = blockIdx.y * BM;
    const int wm = (wid >> 2) * 64;     // warp m-band
    const int wn = (wid & 3) * 32;      // warp n-band

    if ((EPI == 1 || EPI == 2) && tid < 128) {
        int c = bxc + tid;
        float iv = bng[c] * rsqrtf(bnv[c] + 1e-5f);
        ((float*)smem)[tid]         = iv;
        ((float*)(smem + 512))[tid] = bnb[c] - bnm[c] * iv;
    }

    // lane row/quad decomposition for ldsm
    const int aRow = lid & 15;                       // + wm + mf*16
    const int aQ   = lid >> 4;                       // + 2*(ks&1)
    const int bRow = (lid & 7) + ((lid >> 4) << 3);  // + wn + p*16
    const int bQ   = (lid & 8) >> 3;                 // + 2*(ks&1)

    // ---- load issue helpers (128B/row = 8 quads; kblk = kc>>2, in-block quad = kc&3) ----
    auto issueB = [&](int kt, uint32_t stu) {
#pragma unroll
        for (int i = 0; i < 4; i++) {
            int q = tid + i * NTH;                 // 1024 16B quads
            int row = q >> 3, kc = q & 7;
            size_t e = (size_t)(bxc + row) * KDIM + kt * KC + kc * 8;
            CPA16(stu + OFF_B + (kc >> 2) * OPB + swq(row, kc & 3), (const char*)Bw + 2 * e);
        }
    };
    auto issueA1 = [&](int kt, uint32_t stu) {
#pragma unroll
        for (int i = 0; i < 4; i++) {
            int q = tid + i * NTH;
            int row = q >> 3, kc = q & 7;
            size_t e = (size_t)(bym + row) * KDIM + kt * KC + kc * 8;
            CPA16(stu + OFF_A + (kc >> 2) * OPB + swq(row, kc & 3), (const char*)Ah + 2 * e);
        }
    };
    // AMODE 0: A fp32 load/convert in two phased halves (4 float4/thread each)
    auto ldA0h = [&](int kt, float4* aReg, int h) {
#pragma unroll
        for (int i = 0; i < 4; i++) {
            int f = h * 1024 + tid + i * NTH;      // 2048 float4 slots (128 rows x 16)
            int row = f >> 4, kq = f & 15;
            aReg[i] = *(const float4*)(Af + (size_t)(bym + row) * KDIM + kt * KC + kq * 4);
        }
    };
    auto stsA0h = [&](char* st, const float4* aReg, int h) {
#pragma unroll
        for (int i = 0; i < 4; i++) {
            int f = h * 1024 + tid + i * NTH;
            int row = f >> 4, kq = f & 15;         // 8B units within 128B row
            uint32_t h01 = pack_h2(aReg[i].x, aReg[i].y);
            uint32_t h23 = pack_h2(aReg[i].z, aReg[i].w);
            uint32_t d = OFF_A + (kq >> 3) * OPB + swq(row, (kq & 7) >> 1) + (kq & 1) * 8;
            *(uint2*)(st + d) = make_uint2(h01, h23);
        }
    };

    // ---- accumulators ----
    float acc[4][4][4];
#pragma unroll
    for (int mf = 0; mf < 4; mf++)
#pragma unroll
        for (int j = 0; j < 4; j++)
#pragma unroll
            for (int e = 0; e < 4; e++) acc[mf][j][e] = 0.f;

    // one k16-step (ks in 0..3): 6 ldsm4 + 16 MMA
    auto computeKS = [&](int ks, uint32_t s0) {
        const uint32_t blk = (uint32_t)(ks >> 1) * OPB;
        const int kq2 = 2 * (ks & 1);
        uint32_t bf[4][2], af[4][4];
#pragma unroll
        for (int p = 0; p < 2; p++) {
            int row = wn + p * 16 + bRow;
            ldsm4(bf[2*p][0], bf[2*p][1], bf[2*p+1][0], bf[2*p+1][1],
                  s0 + OFF_B + blk + swq(row, kq2 + bQ));
        }
#pragma unroll
        for (int mf = 0; mf < 4; mf++) {
            int row = wm + mf * 16 + aRow;
            ldsm4(af[mf][0], af[mf][1], af[mf][2], af[mf][3],
                  s0 + OFF_A + blk + swq(row, kq2 + aQ));
        }
#pragma unroll
        for (int mf = 0; mf < 4; mf++)
#pragma unroll
            for (int j = 0; j < 4; j++) mma_f16(acc[mf][j], af[mf], bf[j]);
    };

    // ---- prologue: fill stages 0 and 1 ----
#pragma unroll
    for (int pk = 0; pk < NSTAGE - 1; pk++) {
        char* st = smem + SM_STAGE + pk * STAGE_BYTES;
        uint32_t stu = sb + SM_STAGE + pk * STAGE_BYTES;
        if (AMODE == 0) {
            float4 aR[4];
            ldA0h(pk, aR, 0); stsA0h(st, aR, 0);
            ldA0h(pk, aR, 1); stsA0h(st, aR, 1);
        } else {
            issueA1(pk, stu);
        }
        issueB(pk, stu);
        CPA_COMMIT();
    }

    // ---- mainloop ----
    float4 aReg0[4], aReg1[4];
    for (int kt = 0; kt < KT; kt++) {
        const int s = kt % NSTAGE;
        const uint32_t s0 = sb + SM_STAGE + s * STAGE_BYTES;
        const int kpre = kt + NSTAGE - 1;
        const int slot = kpre % NSTAGE;
        char* stp = smem + SM_STAGE + slot * STAGE_BYTES;
        uint32_t stu = sb + SM_STAGE + slot * STAGE_BYTES;

        if (AMODE == 0 && kpre < KT) ldA0h(kpre, aReg0, 0);   // half0 hoisted above the wait

        CPA_WAIT1();           // groups through chunk kt complete
        __syncthreads();       // chunk kt visible to all; stage (kt-1)%3 free

        if (AMODE == 0) {
            if (kpre < KT) { stsA0h(stp, aReg0, 0); issueB(kpre, stu); }
            CPA_COMMIT();
            computeKS(0, s0);
            computeKS(1, s0);
            if (kpre < KT) ldA0h(kpre, aReg1, 1);    // half1 load under ks2's shadow
            computeKS(2, s0);
            if (kpre < KT) stsA0h(stp, aReg1, 1);    // STS drains by the next barriers
            computeKS(3, s0);
        } else {
            // deferred refill: cp.async bursts ride under the MMA shadow
            computeKS(0, s0);
            if (kpre < KT) issueA1(kpre, stu);
            computeKS(1, s0);
            if (kpre < KT) issueB(kpre, stu);
            CPA_COMMIT();
            computeKS(2, s0);
            computeKS(3, s0);
        }
    }
    CPA_WAIT0();

    // ---- epilogue: fragments -> global ----
    const float* invv = (const float*)smem;
    const float* addv = (const float*)(smem + 512);
#pragma unroll
    for (int mf = 0; mf < 4; mf++) {
#pragma unroll
        for (int j = 0; j < 4; j++) {
            const float* a = acc[mf][j];
            const int rg = bym + wm + mf * 16 + (lid >> 2);
            const int cl = wn + j * 8 + (lid & 3) * 2;
            const int cg = bxc + cl;
#pragma unroll
            for (int half = 0; half < 2; half++) {
                const int r = rg + half * 8;
                float v0 = a[half * 2 + 0], v1 = a[half * 2 + 1];
                const size_t go = (size_t)r * DDIM + cg;
                if (EPI == 0) {
                    v0 = fmaxf(v0, 0.f); v1 = fmaxf(v1, 0.f);
                    *(uint32_t*)((char*)OutHalf + 2 * go) = pack_h2(v0, v1);
                } else if (EPI == 1) {
                    v0 = fmaxf(fmaf(v0, invv[cl], addv[cl]), 0.f);
                    v1 = fmaxf(fmaf(v1, invv[cl + 1], addv[cl + 1]), 0.f);
                    *(uint32_t*)((char*)OutHalf + 2 * go) = pack_h2(v0, v1);
                } else if (EPI == 2) {
                    float2 o;
                    o.x = fmaxf(fmaf(v0, invv[cl], addv[cl]), 0.f);
                    o.y = fmaxf(fmaf(v1, invv[cl + 1], addv[cl + 1]), 0.f);
                    *(float2*)(OutF + go) = o;
                } else {
                    const __half2 pv = *(const __half2*)((const char*)Ph + 2 * go);
                    const float2 vv = *(const float2*)(Vf + go);
                    const float p0 = __half2float(__low2half(pv));
                    const float p1 = __half2float(__high2half(pv));
                    const float s0v = 1.f / (1.f + __expf(-v0));
                    const float s1v = 1.f / (1.f + __expf(-v1));
                    float2 o;
                    o.x = fmaf(p0, s0v, vv.x);
                    o.y = fmaf(p1, s1v, vv.y);
                    *(float2*)(OutF + go) = o;
                }
            }
        }
    }
}

// ---------------- launch (stream-fork: G1 || G2->G3, join, G4) ----------------
extern "C" void kernel_launch(void* const* d_in, const int* in_sizes, int n_in,
                              void* d_out, int out_size)
{
    const float* F1   = (const float*)d_in[0];
    const float* F2   = (const float*)d_in[1];
    const float* Wk   = (const float*)d_in[2];
    const float* Wv1  = (const float*)d_in[3];
    const float* Wv2  = (const float*)d_in[4];
    const float* bn1g = (const float*)d_in[5];
    const float* bn1b = (const float*)d_in[6];
    const float* bn1m = (const float*)d_in[7];
    const float* bn1v = (const float*)d_in[8];
    const float* bn2g = (const float*)d_in[9];
    const float* bn2b = (const float*)d_in[10];
    const float* bn2m = (const float*)d_in[11];
    const float* bn2v = (const float*)d_in[12];
    // d_in[13]=Wa, d_in[14]=Wqk unused: softmax over identical L-columns is uniform 1/L.
    const float* Wvc  = (const float*)d_in[15];
    float* out = (float*)d_out;

    __half *P, *H, *W;
    float* V;
    cudaGetSymbolAddress((void**)&P, g_P);
    cudaGetSymbolAddress((void**)&H, g_H);
    cudaGetSymbolAddress((void**)&V, g_V);
    cudaGetSymbolAddress((void**)&W, g_W);
    const int WSZ = 512 * 512;

    cudaFuncSetAttribute(gemm_hmma<0,0>, cudaFuncAttributeMaxDynamicSharedMemorySize, SM_TOTAL);
    cudaFuncSetAttribute(gemm_hmma<0,1>, cudaFuncAttributeMaxDynamicSharedMemorySize, SM_TOTAL);
    cudaFuncSetAttribute(gemm_hmma<1,2>, cudaFuncAttributeMaxDynamicSharedMemorySize, SM_TOTAL);
    cudaFuncSetAttribute(gemm_hmma<1,3>, cudaFuncAttributeMaxDynamicSharedMemorySize, SM_TOTAL);

    // stream/event resources: created once on the first (uncaptured correctness) call,
    // reused identically on every call -> deterministic, capture-legal fork/join
    static cudaStream_t s2 = nullptr;
    static cudaEvent_t evW = nullptr, ev3 = nullptr;
    if (!s2) {
        cudaStreamCreateWithFlags(&s2, cudaStreamNonBlocking);
        cudaEventCreateWithFlags(&evW, cudaEventDisableTiming);
        cudaEventCreateWithFlags(&ev3, cudaEventDisableTiming);
    }

    dim3 grid(DDIM / BN, NROWS / BM);   // (4, 512)
    dim3 block(NTH);

    // weight fp16 convert: mat0=Wk, mat1=Wv1, mat2=Wv2, mat3=Wvc
    conv_weights<<<4096, 256>>>(Wk, Wv1, Wv2, Wvc);
    cudaEventRecord(evW, 0);
    cudaStreamWaitEvent(s2, evW, 0);

    // G1 (default stream): P = fp16(relu(F1 @ Wk^T))
    gemm_hmma<0,0><<<grid, block, SM_TOTAL>>>(F1, nullptr, W + 0 * WSZ,
        nullptr, P, nullptr, nullptr, nullptr, nullptr, nullptr, nullptr);

    // G2 (s2): H = fp16(relu(bn1(F2 @ Wv1^T)))
    gemm_hmma<0,1><<<grid, block, SM_TOTAL, s2>>>(F2, nullptr, W + 1 * WSZ,
        nullptr, H, bn1g, bn1b, bn1m, bn1v, nullptr, nullptr);
    // G3 (s2, after G2): V = relu(bn2(H @ Wv2^T))
    gemm_hmma<1,2><<<grid, block, SM_TOTAL, s2>>>(nullptr, H, W + 2 * WSZ,
        V, nullptr, bn2g, bn2b, bn2m, bn2v, nullptr, nullptr);
    cudaEventRecord(ev3, s2);

    // join: G4 needs P (G1, default stream) and V (G3, s2)
    cudaStreamWaitEvent(0, ev3, 0);
    // G4: out = V + P * sigmoid(P @ Wvc^T)
    gemm_hmma<1,3><<<grid, block, SM_TOTAL>>>(nullptr, P, W + 3 * WSZ,
        out, nullptr, nullptr, nullptr, nullptr, nullptr, P, V);
}

// round 17
// speedup vs baseline: 5.2412x; 1.0024x over previous
#include <cuda_runtime.h>
#include <cuda_fp16.h>
#include <cstdint>

#define NROWS 65536
#define KDIM  512
#define DDIM  512

// ---------------- device scratch (allocation-free) ----------------
__device__ __half g_P[(size_t)NROWS * DDIM];    // P  (fp16)
__device__ __half g_H[(size_t)NROWS * DDIM];    // H  (fp16)
__device__ __half g_V[(size_t)NROWS * DDIM];    // V  (fp16)
__device__ __half g_W[4][512 * 512];            // weights (fp16)

// ---------------- PTX helpers (baseline sm_80+, no 'a'-arch features) ----------------
__device__ __forceinline__ uint32_t smem_u32(const void* p) {
    uint32_t a;
    asm("{ .reg .u64 t; cvta.to.shared.u64 t, %1; cvt.u32.u64 %0, t; }" : "=r"(a) : "l"(p));
    return a;
}
__device__ __forceinline__ void ldsm4(uint32_t& r0, uint32_t& r1, uint32_t& r2, uint32_t& r3,
                                      uint32_t addr) {
    asm volatile("ldmatrix.sync.aligned.m8n8.x4.shared.b16 {%0,%1,%2,%3}, [%4];"
                 : "=r"(r0), "=r"(r1), "=r"(r2), "=r"(r3) : "r"(addr));
}
__device__ __forceinline__ void mma_f16(float* c, const uint32_t* a, const uint32_t* b) {
    asm volatile("mma.sync.aligned.m16n8k16.row.col.f32.f16.f16.f32 "
                 "{%0,%1,%2,%3}, {%4,%5,%6,%7}, {%8,%9}, {%0,%1,%2,%3};"
                 : "+f"(c[0]), "+f"(c[1]), "+f"(c[2]), "+f"(c[3])
                 : "r"(a[0]), "r"(a[1]), "r"(a[2]), "r"(a[3]), "r"(b[0]), "r"(b[1]));
}
#define CPA16(dst, src)  asm volatile("cp.async.cg.shared.global [%0], [%1], 16;" :: "r"(dst), "l"(src) : "memory")
#define CPA_COMMIT()     asm volatile("cp.async.commit_group;" ::: "memory")
#define CPA_WAIT1()      asm volatile("cp.async.wait_group 1;" ::: "memory")
#define CPA_WAIT0()      asm volatile("cp.async.wait_group 0;" ::: "memory")

// pack two floats to f16x2 (low half = a)
__device__ __forceinline__ uint32_t pack_h2(float a, float b) {
    uint32_t r;
    asm("cvt.rn.f16x2.f32 %0, %1, %2;" : "=r"(r) : "f"(b), "f"(a));
    return r;
}

// ---------------- layout constants (R16-verified) ----------------
constexpr int BM = 128, BN = 128, KC = 64, KT = KDIM / KC;   // 8 k-chunks
constexpr int NTH = 256;
constexpr int NSTAGE = 3;
// Each chunk stored as TWO 32-col blocks of 64B rows with the verified XOR swizzle:
// swq(row,q) = row*64 + (q ^ ((row>>1)&3))*16
constexpr int OPB = 128 * 64;               // 8192 = one 32-col block (128 rows)
constexpr int OFF_A = 0;                    // A: 2 blocks = 16384
constexpr int OFF_B = 2 * OPB;              // B: 2 blocks = 16384
constexpr int STAGE_BYTES = 4 * OPB;        // 32768
constexpr int SM_STAGE = 1024;              // bn coeffs live in [0,1024)
constexpr int SM_TOTAL = SM_STAGE + NSTAGE * STAGE_BYTES;   // 99328 -> 2 CTAs/SM

__device__ __forceinline__ uint32_t swq(int row, int q) {
    return (uint32_t)((row << 6) + ((q ^ ((row >> 1) & 3)) << 4));
}

// ---------------- weight fp16 convert ----------------
__global__ void conv_weights(const float* __restrict__ w0, const float* __restrict__ w1,
                             const float* __restrict__ w2, const float* __restrict__ w3) {
    int idx = blockIdx.x * blockDim.x + threadIdx.x;
    int mat = idx >> 18;
    int off = idx & 0x3FFFF;
    const float* s = (mat == 0) ? w0 : (mat == 1) ? w1 : (mat == 2) ? w2 : w3;
    g_W[mat][off] = __float2half_rn(s[off]);
}

// ---------------- fp16 HMMA GEMM, KC=64, 3-stage 1-sync, 2 CTAs/SM ----------------
// D[n,d] = epi( sum_k A[n,k] * B[d,k] ),  A,B fp16, fp32 accum
// AMODE 0: A fp32 (convert to fp16 in-kernel, phased halves)   AMODE 1: A native fp16
// EPI 0: relu -> OutHalf          EPI 1: relu(bn) -> OutHalf
// EPI 2: relu(bn) -> OutHalf      EPI 3: OutF = Vh + P*sigmoid(acc)
template <int AMODE, int EPI>
__global__ __launch_bounds__(NTH, 2)
void gemm_hmma(const float* __restrict__ Af,
               const __half* __restrict__ Ah,
               const __half* __restrict__ Bw,
               float* __restrict__ OutF, __half* __restrict__ OutHalf,
               const float* __restrict__ bng, const float* __restrict__ bnb,
               const float* __restrict__ bnm, const float* __restrict__ bnv,
               const __half* __restrict__ Ph, const __half* __restrict__ Vh)
{
    extern __shared__ char smem[];
    const uint32_t sb = smem_u32(smem);
    const int tid = threadIdx.x;
    const int wid = tid >> 5, lid = tid & 31;
    const int bxc = blockIdx.x * BN;
    const int bym = blockIdx.y * BM;
    const int wm = (wid >> 2) * 64;     // warp m-band
    const int wn = (wid & 3) * 32;      // warp n-band

    if ((EPI == 1 || EPI == 2) && tid < 128) {
        int c = bxc + tid;
        float iv = bng[c] * rsqrtf(bnv[c] + 1e-5f);
        ((float*)smem)[tid]         = iv;
        ((float*)(smem + 512))[tid] = bnb[c] - bnm[c] * iv;
    }

    // lane row/quad decomposition for ldsm
    const int aRow = lid & 15;                       // + wm + mf*16
    const int aQ   = lid >> 4;                       // + 2*(ks&1)
    const int bRow = (lid & 7) + ((lid >> 4) << 3);  // + wn + p*16
    const int bQ   = (lid & 8) >> 3;                 // + 2*(ks&1)

    // ---- load issue helpers (128B/row = 8 quads; kblk = kc>>2, in-block quad = kc&3) ----
    auto issueB = [&](int kt, uint32_t stu) {
#pragma unroll
        for (int i = 0; i < 4; i++) {
            int q = tid + i * NTH;                 // 1024 16B quads
            int row = q >> 3, kc = q & 7;
            size_t e = (size_t)(bxc + row) * KDIM + kt * KC + kc * 8;
            CPA16(stu + OFF_B + (kc >> 2) * OPB + swq(row, kc & 3), (const char*)Bw + 2 * e);
        }
    };
    auto issueA1 = [&](int kt, uint32_t stu) {
#pragma unroll
        for (int i = 0; i < 4; i++) {
            int q = tid + i * NTH;
            int row = q >> 3, kc = q & 7;
            size_t e = (size_t)(bym + row) * KDIM + kt * KC + kc * 8;
            CPA16(stu + OFF_A + (kc >> 2) * OPB + swq(row, kc & 3), (const char*)Ah + 2 * e);
        }
    };
    // AMODE 0: A fp32 load/convert in two phased halves (4 float4/thread each)
    auto ldA0h = [&](int kt, float4* aReg, int h) {
#pragma unroll
        for (int i = 0; i < 4; i++) {
            int f = h * 1024 + tid + i * NTH;      // 2048 float4 slots (128 rows x 16)
            int row = f >> 4, kq = f & 15;
            aReg[i] = *(const float4*)(Af + (size_t)(bym + row) * KDIM + kt * KC + kq * 4);
        }
    };
    auto stsA0h = [&](char* st, const float4* aReg, int h) {
#pragma unroll
        for (int i = 0; i < 4; i++) {
            int f = h * 1024 + tid + i * NTH;
            int row = f >> 4, kq = f & 15;         // 8B units within 128B row
            uint32_t h01 = pack_h2(aReg[i].x, aReg[i].y);
            uint32_t h23 = pack_h2(aReg[i].z, aReg[i].w);
            uint32_t d = OFF_A + (kq >> 3) * OPB + swq(row, (kq & 7) >> 1) + (kq & 1) * 8;
            *(uint2*)(st + d) = make_uint2(h01, h23);
        }
    };

    // ---- accumulators ----
    float acc[4][4][4];
#pragma unroll
    for (int mf = 0; mf < 4; mf++)
#pragma unroll
        for (int j = 0; j < 4; j++)
#pragma unroll
            for (int e = 0; e < 4; e++) acc[mf][j][e] = 0.f;

    // one k16-step (ks in 0..3): 6 ldsm4 + 16 MMA
    auto computeKS = [&](int ks, uint32_t s0) {
        const uint32_t blk = (uint32_t)(ks >> 1) * OPB;
        const int kq2 = 2 * (ks & 1);
        uint32_t bf[4][2], af[4][4];
#pragma unroll
        for (int p = 0; p < 2; p++) {
            int row = wn + p * 16 + bRow;
            ldsm4(bf[2*p][0], bf[2*p][1], bf[2*p+1][0], bf[2*p+1][1],
                  s0 + OFF_B + blk + swq(row, kq2 + bQ));
        }
#pragma unroll
        for (int mf = 0; mf < 4; mf++) {
            int row = wm + mf * 16 + aRow;
            ldsm4(af[mf][0], af[mf][1], af[mf][2], af[mf][3],
                  s0 + OFF_A + blk + swq(row, kq2 + aQ));
        }
#pragma unroll
        for (int mf = 0; mf < 4; mf++)
#pragma unroll
            for (int j = 0; j < 4; j++) mma_f16(acc[mf][j], af[mf], bf[j]);
    };

    // ---- prologue: fill stages 0 and 1 ----
#pragma unroll
    for (int pk = 0; pk < NSTAGE - 1; pk++) {
        char* st = smem + SM_STAGE + pk * STAGE_BYTES;
        uint32_t stu = sb + SM_STAGE + pk * STAGE_BYTES;
        if (AMODE == 0) {
            float4 aR[4];
            ldA0h(pk, aR, 0); stsA0h(st, aR, 0);
            ldA0h(pk, aR, 1); stsA0h(st, aR, 1);
        } else {
            issueA1(pk, stu);
        }
        issueB(pk, stu);
        CPA_COMMIT();
    }

    // ---- mainloop (R16-verified) ----
    float4 aReg0[4], aReg1[4];
    for (int kt = 0; kt < KT; kt++) {
        const int s = kt % NSTAGE;
        const uint32_t s0 = sb + SM_STAGE + s * STAGE_BYTES;
        const int kpre = kt + NSTAGE - 1;
        const int slot = kpre % NSTAGE;
        char* stp = smem + SM_STAGE + slot * STAGE_BYTES;
        uint32_t stu = sb + SM_STAGE + slot * STAGE_BYTES;

        if (AMODE == 0 && kpre < KT) ldA0h(kpre, aReg0, 0);   // half0 hoisted above the wait

        CPA_WAIT1();           // groups through chunk kt complete
        __syncthreads();       // chunk kt visible to all; stage (kt-1)%3 free

        if (AMODE == 0) {
            if (kpre < KT) { stsA0h(stp, aReg0, 0); issueB(kpre, stu); }
            CPA_COMMIT();
            computeKS(0, s0);
            computeKS(1, s0);
            if (kpre < KT) ldA0h(kpre, aReg1, 1);    // half1 load under ks2's shadow
            computeKS(2, s0);
            if (kpre < KT) stsA0h(stp, aReg1, 1);    // STS drains by the next barriers
            computeKS(3, s0);
        } else {
            // deferred refill: cp.async bursts ride under the MMA shadow
            computeKS(0, s0);
            if (kpre < KT) issueA1(kpre, stu);
            computeKS(1, s0);
            if (kpre < KT) issueB(kpre, stu);
            CPA_COMMIT();
            computeKS(2, s0);
            computeKS(3, s0);
        }
    }
    CPA_WAIT0();

    // ---- epilogue: fragments -> global ----
    const float* invv = (const float*)smem;
    const float* addv = (const float*)(smem + 512);
#pragma unroll
    for (int mf = 0; mf < 4; mf++) {
#pragma unroll
        for (int j = 0; j < 4; j++) {
            const float* a = acc[mf][j];
            const int rg = bym + wm + mf * 16 + (lid >> 2);
            const int cl = wn + j * 8 + (lid & 3) * 2;
            const int cg = bxc + cl;
#pragma unroll
            for (int half = 0; half < 2; half++) {
                const int r = rg + half * 8;
                float v0 = a[half * 2 + 0], v1 = a[half * 2 + 1];
                const size_t go = (size_t)r * DDIM + cg;
                if (EPI == 0) {
                    v0 = fmaxf(v0, 0.f); v1 = fmaxf(v1, 0.f);
                    *(uint32_t*)((char*)OutHalf + 2 * go) = pack_h2(v0, v1);
                } else if (EPI == 1 || EPI == 2) {
                    v0 = fmaxf(fmaf(v0, invv[cl], addv[cl]), 0.f);
                    v1 = fmaxf(fmaf(v1, invv[cl + 1], addv[cl + 1]), 0.f);
                    *(uint32_t*)((char*)OutHalf + 2 * go) = pack_h2(v0, v1);
                } else {
                    const __half2 pv = *(const __half2*)((const char*)Ph + 2 * go);
                    const __half2 vv = *(const __half2*)((const char*)Vh + 2 * go);
                    const float p0 = __half2float(__low2half(pv));
                    const float p1 = __half2float(__high2half(pv));
                    const float s0v = 1.f / (1.f + __expf(-v0));
                    const float s1v = 1.f / (1.f + __expf(-v1));
                    float2 o;
                    o.x = fmaf(p0, s0v, __half2float(__low2half(vv)));
                    o.y = fmaf(p1, s1v, __half2float(__high2half(vv)));
                    *(float2*)(OutF + go) = o;
                }
            }
        }
    }
}

// ---------------- launch (stream-fork: G1 || G2->G3, join, G4) ----------------
extern "C" void kernel_launch(void* const* d_in, const int* in_sizes, int n_in,
                              void* d_out, int out_size)
{
    const float* F1   = (const float*)d_in[0];
    const float* F2   = (const float*)d_in[1];
    const float* Wk   = (const float*)d_in[2];
    const float* Wv1  = (const float*)d_in[3];
    const float* Wv2  = (const float*)d_in[4];
    const float* bn1g = (const float*)d_in[5];
    const float* bn1b = (const float*)d_in[6];
    const float* bn1m = (const float*)d_in[7];
    const float* bn1v = (const float*)d_in[8];
    const float* bn2g = (const float*)d_in[9];
    const float* bn2b = (const float*)d_in[10];
    const float* bn2m = (const float*)d_in[11];
    const float* bn2v = (const float*)d_in[12];
    // d_in[13]=Wa, d_in[14]=Wqk unused: softmax over identical L-columns is uniform 1/L.
    const float* Wvc  = (const float*)d_in[15];
    float* out = (float*)d_out;

    __half *P, *H, *V, *W;
    cudaGetSymbolAddress((void**)&P, g_P);
    cudaGetSymbolAddress((void**)&H, g_H);
    cudaGetSymbolAddress((void**)&V, g_V);
    cudaGetSymbolAddress((void**)&W, g_W);
    const int WSZ = 512 * 512;

    cudaFuncSetAttribute(gemm_hmma<0,0>, cudaFuncAttributeMaxDynamicSharedMemorySize, SM_TOTAL);
    cudaFuncSetAttribute(gemm_hmma<0,1>, cudaFuncAttributeMaxDynamicSharedMemorySize, SM_TOTAL);
    cudaFuncSetAttribute(gemm_hmma<1,2>, cudaFuncAttributeMaxDynamicSharedMemorySize, SM_TOTAL);
    cudaFuncSetAttribute(gemm_hmma<1,3>, cudaFuncAttributeMaxDynamicSharedMemorySize, SM_TOTAL);

    // stream/event resources: created once on the first (uncaptured correctness) call,
    // reused identically on every call -> deterministic, capture-legal fork/join
    static cudaStream_t s2 = nullptr;
    static cudaEvent_t evW = nullptr, ev3 = nullptr;
    if (!s2) {
        cudaStreamCreateWithFlags(&s2, cudaStreamNonBlocking);
        cudaEventCreateWithFlags(&evW, cudaEventDisableTiming);
        cudaEventCreateWithFlags(&ev3, cudaEventDisableTiming);
    }

    dim3 grid(DDIM / BN, NROWS / BM);   // (4, 512)
    dim3 block(NTH);

    // weight fp16 convert: mat0=Wk, mat1=Wv1, mat2=Wv2, mat3=Wvc
    conv_weights<<<4096, 256>>>(Wk, Wv1, Wv2, Wvc);
    cudaEventRecord(evW, 0);
    cudaStreamWaitEvent(s2, evW, 0);

    // G1 (default stream): P = fp16(relu(F1 @ Wk^T))
    gemm_hmma<0,0><<<grid, block, SM_TOTAL>>>(F1, nullptr, W + 0 * WSZ,
        nullptr, P, nullptr, nullptr, nullptr, nullptr, nullptr, nullptr);

    // G2 (s2): H = fp16(relu(bn1(F2 @ Wv1^T)))
    gemm_hmma<0,1><<<grid, block, SM_TOTAL, s2>>>(F2, nullptr, W + 1 * WSZ,
        nullptr, H, bn1g, bn1b, bn1m, bn1v, nullptr, nullptr);
    // G3 (s2, after G2): V = fp16(relu(bn2(H @ Wv2^T)))
    gemm_hmma<1,2><<<grid, block, SM_TOTAL, s2>>>(nullptr, H, W + 2 * WSZ,
        nullptr, V, bn2g, bn2b, bn2m, bn2v, nullptr, nullptr);
    cudaEventRecord(ev3, s2);

    // join: G4 needs P (G1, default stream) and V (G3, s2)
    cudaStreamWaitEvent(0, ev3, 0);
    // G4: out = V + P * sigmoid(P @ Wvc^T)
    gemm_hmma<1,3><<<grid, block, SM_TOTAL>>>(nullptr, P, W + 3 * WSZ,
        out, nullptr, nullptr, nullptr, nullptr, nullptr, P, V);
}